// round 6
// baseline (speedup 1.0000x reference)
#include <cuda_runtime.h>
#include <math.h>

#define NBATCH 8
#define NPTS   131072
#define TOTPTS (NBATCH*NPTS)
#define NGRP   30
#define NGB    (NBATCH*NGRP)   // 240
#define KNN    100
#define STRIDE 4369            // 131072/30
#define HB     2048            // float-radix bins: bits(d2) >> 21
#define SVCAP  2048            // survivor cap (expected ~700)
#define RCAP   4096            // rescue-ball cap
#define SUBCAP 1024
#define PTC    8
#define CHUNK  (NPTS/PTC)
#define NT     256
#define MTGT   700.0f

// uniform grid
#define GR     48
#define GCELLS (GR*GR*GR)        // 110592
#define NCELLS (NBATCH*GCELLS)   // 884736
#define GLOW   (-6.0f)
#define INVH   4.0f              // cell = 0.25
#define SCB    1024              // scan elems per block
#define SNB    (NCELLS/SCB)      // 864

// brute fallback caps — should never fire
#define FCAP   6144
#define FSCAP  512
#define FB_DYN (4*FCAP*4)

#define SEL_DYN ((5*SVCAP + HB)*4)
#define RES_DYN ((5*RCAP  + HB)*4)

// -------- static device scratch --------
__device__ float    d_Ta[NGB];
__device__ unsigned d_nsv[NGB];
__device__ unsigned d_nsv2[NGB];
__device__ int      d_flag[NGB];        // 0 ok, 1 rescue pass-2, 2 brute
__device__ float    d_T2[NGB];
__device__ float    d_meanf[NGB][3];
__device__ float4   d_sv[NGB][SVCAP];
__device__ float4   d_sv2[NGB][RCAP];
__device__ double   d_gmean[NGB][3];
__device__ double   d_gcov[NGB][6];
__device__ float    d_dirs[NGB][3];
__device__ double   d_fs[NGB];

__device__ unsigned d_cellcnt[NCELLS];
__device__ unsigned d_cellstart[NCELLS];
__device__ unsigned d_cellcur[NCELLS];
__device__ unsigned d_bsum[SNB];
__device__ unsigned d_ptidx[TOTPTS];

__device__ __forceinline__ unsigned d2bin(float d2) {
    return __float_as_uint(d2) >> 21;
}
__device__ __forceinline__ int cellco(float x) {
    int c = (int)floorf((x - GLOW) * INVH);
    return min(GR-1, max(0, c));
}

// ===========================================================================
// prep: per-group analytic radius with expected MTGT points inside.
// ===========================================================================
__global__ void prep_kernel(const float* __restrict__ pts_all) {
    int t = threadIdx.x;
    if (t >= NGB) return;
    d_nsv[t] = 0u;
    d_nsv2[t] = 0u;
    d_flag[t] = 0;
    int b = t / NGRP, g = t % NGRP;
    int ci = g * STRIDE;
    const float* pts = pts_all + (size_t)b * NPTS * 3;
    float qx = pts[3*ci], qy = pts[3*ci+1], qz = pts[3*ci+2];
    float rho = sqrtf(qx*qx + qy*qy + qz*qz);
    rho = fmaxf(rho, 0.02f);
    const float A = (float)NPTS * 0.3989422804014327f / rho;
    float cum = 0.0f;
    float ds = 0.015f;
    float s = 0.5f * ds;
    float r = 8.0f;
    for (int it = 0; it < 540; it++) {
        float em = expf(-0.5f*(s-rho)*(s-rho)) - expf(-0.5f*(s+rho)*(s+rho));
        cum += A * s * em * ds;
        if (cum >= MTGT) { r = s + 0.5f*ds; break; }
        s += ds;
    }
    d_Ta[t] = r * r;
}

// ===========================================================================
// grid build
// ===========================================================================
__global__ void zero_cnt_kernel() {
    d_cellcnt[blockIdx.x * SCB + threadIdx.x] = 0u;
}

__global__ void hist_kernel(const float* __restrict__ pts_all) {
    int i = blockIdx.x * blockDim.x + threadIdx.x;
    if (i >= TOTPTS) return;
    const float* p = pts_all + 3u * (unsigned)i;
    int cx = cellco(p[0]), cy = cellco(p[1]), cz = cellco(p[2]);
    int b = i >> 17;
    int cell = ((b*GR + cz)*GR + cy)*GR + cx;
    atomicAdd(&d_cellcnt[cell], 1u);
}

__global__ void scanA_kernel() {
    __shared__ unsigned sh[SCB];
    int t = threadIdx.x;
    sh[t] = d_cellcnt[blockIdx.x * SCB + t];
    __syncthreads();
    for (int s = SCB/2; s > 0; s >>= 1) {
        if (t < s) sh[t] += sh[t+s];
        __syncthreads();
    }
    if (t == 0) d_bsum[blockIdx.x] = sh[0];
}

__global__ void scanB_kernel() {
    __shared__ unsigned sh[1024];
    int t = threadIdx.x;
    unsigned v = (t < SNB) ? d_bsum[t] : 0u;
    sh[t] = v; __syncthreads();
    for (int off = 1; off < 1024; off <<= 1) {
        unsigned u = sh[t];
        if (t >= off) u += sh[t - off];
        __syncthreads();
        sh[t] = u;
        __syncthreads();
    }
    if (t < SNB) d_bsum[t] = sh[t] - v;   // exclusive
}

__global__ void scanC_kernel() {
    __shared__ unsigned sh[SCB];
    int t = threadIdx.x;
    unsigned base = blockIdx.x * SCB + t;
    unsigned v = d_cellcnt[base];
    sh[t] = v; __syncthreads();
    for (int off = 1; off < SCB; off <<= 1) {
        unsigned u = sh[t];
        if (t >= off) u += sh[t - off];
        __syncthreads();
        sh[t] = u;
        __syncthreads();
    }
    unsigned st = d_bsum[blockIdx.x] + sh[t] - v;
    d_cellstart[base] = st;
    d_cellcur[base]  = st;
}

__global__ void scatter_kernel(const float* __restrict__ pts_all) {
    int i = blockIdx.x * blockDim.x + threadIdx.x;
    if (i >= TOTPTS) return;
    const float* p = pts_all + 3u * (unsigned)i;
    int cx = cellco(p[0]), cy = cellco(p[1]), cz = cellco(p[2]);
    int b = i >> 17;
    int cell = ((b*GR + cz)*GR + cy)*GR + cx;
    unsigned pos = atomicAdd(&d_cellcur[cell], 1u);
    d_ptidx[pos] = (unsigned)(i & (NPTS-1));   // batch-local index
}

// ===========================================================================
// gather: per group, visit only cells intersecting the Ta-ball AABB.
// Produces the SAME survivor set as a full Ta-scan (same d2<Ta test).
// ===========================================================================
__global__ void __launch_bounds__(NT) gather_kernel(const float* __restrict__ pts_all) {
    const int gb = blockIdx.x;
    const int b = gb / NGRP, g = gb % NGRP;
    const float* __restrict__ pts = pts_all + (size_t)b * NPTS * 3;
    const int ci = g * STRIDE;
    const float qx = pts[3*ci], qy = pts[3*ci+1], qz = pts[3*ci+2];
    const float Ta = d_Ta[gb];
    const float r  = sqrtf(Ta) * 1.00001f;

    const int xlo = cellco(qx - r), xhi = cellco(qx + r);
    const int ylo = cellco(qy - r), yhi = cellco(qy + r);
    const int zlo = cellco(qz - r), zhi = cellco(qz + r);
    const int nx = xhi - xlo + 1;
    const int ny = yhi - ylo + 1;
    const int nz = zhi - zlo + 1;
    const int total = nx * ny * nz;

    for (int lin = threadIdx.x; lin < total; lin += NT) {
        int cz = lin / (nx*ny);
        int rem = lin % (nx*ny);
        int cy = rem / nx;
        int cx = rem % nx;
        int cell = ((b*GR + (zlo+cz))*GR + (ylo+cy))*GR + (xlo+cx);
        unsigned st = d_cellstart[cell];
        unsigned cn = d_cellcnt[cell];
        for (unsigned j = 0; j < cn; j++) {
            unsigned li = d_ptidx[st + j];
            float px = pts[3u*li], py = pts[3u*li+1], pz = pts[3u*li+2];
            float dx = px-qx, dy = py-qy, dz = pz-qz;
            float d2 = fmaf(dx, dx, fmaf(dy, dy, dz*dz));
            if (d2 < Ta) {
                unsigned s = atomicAdd(&d_nsv[gb], 1u);
                if (s < SVCAP)
                    d_sv[gb][s] = make_float4(px, py, pz, __int_as_float((int)li));
            }
        }
    }
}

// ===========================================================================
// shared selection machinery
// ===========================================================================
struct SelSh {
    unsigned partial[NT];
    int      subSlot[SUBCAP];
    int      order[KNN];
    double   red[NT];
    float    q2s[4];
    double   Dc;
    unsigned nsub;
    int      pivotS;
    int      bflag;
};

__device__ __forceinline__ double tree_red(double* red, int tid, double v) {
    red[tid] = v;
    __syncthreads();
    #pragma unroll
    for (int s = NT/2; s > 0; s >>= 1) {
        if (tid < s) red[tid] += red[tid + s];
        __syncthreads();
    }
    double r = red[0];
    __syncthreads();
    return r;
}

__device__ __forceinline__ bool select_topk(const float* sd, const int* si,
                                            unsigned* hist, SelSh* sh,
                                            int S, int tid) {
    for (int i = tid; i < HB; i += NT) hist[i] = 0u;
    if (tid == 0) sh->nsub = 0u;
    __syncthreads();
    for (int s = tid; s < S; s += NT) atomicAdd(&hist[d2bin(sd[s])], 1u);
    __syncthreads();
    {
        unsigned ps = 0;
        #pragma unroll
        for (int j = 0; j < HB/NT; j++) ps += hist[tid*(HB/NT) + j];
        sh->partial[tid] = ps;
    }
    __syncthreads();
    if (tid == 0) {
        unsigned c = 0; int t = 0;
        while (c + sh->partial[t] < KNN) { c += sh->partial[t]; t++; }
        int bin = t * (HB/NT);
        while (c + hist[bin] < KNN) { c += hist[bin]; bin++; }
        sh->pivotS = bin;
    }
    __syncthreads();
    const unsigned piv = (unsigned)sh->pivotS;
    for (int s = tid; s < S; s += NT) {
        if (d2bin(sd[s]) <= piv) {
            unsigned u = atomicAdd(&sh->nsub, 1u);
            if (u < SUBCAP) sh->subSlot[u] = s;
        }
    }
    __syncthreads();
    if (sh->nsub > SUBCAP) return false;
    const int U = (int)sh->nsub;
    for (int u = tid; u < U; u += NT) {
        int slot = sh->subSlot[u];
        float d = sd[slot]; int id = si[slot];
        int rank = 0;
        for (int v = 0; v < U; v++) {
            int s2 = sh->subSlot[v];
            float dv = sd[s2];
            rank += (dv < d) || (dv == d && si[s2] < id);
        }
        if (rank < KNN) sh->order[rank] = slot;
    }
    __syncthreads();
    return true;
}

__device__ __forceinline__ void cov_store(const float* sx, const float* sy,
                                          const float* sz, SelSh* sh,
                                          int tid, int gb) {
    double X = (tid < KNN) ? (double)sx[sh->order[tid]] : 0.0;
    double Y = (tid < KNN) ? (double)sy[sh->order[tid]] : 0.0;
    double Z = (tid < KNN) ? (double)sz[sh->order[tid]] : 0.0;
    double s0 = tree_red(sh->red, tid, X);
    double s1 = tree_red(sh->red, tid, Y);
    double s2 = tree_red(sh->red, tid, Z);
    double s3 = tree_red(sh->red, tid, X*X);
    double s4 = tree_red(sh->red, tid, X*Y);
    double s5 = tree_red(sh->red, tid, X*Z);
    double s6 = tree_red(sh->red, tid, Y*Y);
    double s7 = tree_red(sh->red, tid, Y*Z);
    double s8 = tree_red(sh->red, tid, Z*Z);
    if (tid == 0) {
        const double K = (double)KNN;
        double ax = s0/K, ay = s1/K, az = s2/K;
        d_gcov[gb][0] = s3/K - ax*ax;
        d_gcov[gb][1] = s4/K - ax*ay;
        d_gcov[gb][2] = s5/K - ax*az;
        d_gcov[gb][3] = s6/K - ay*ay;
        d_gcov[gb][4] = s7/K - ay*az;
        d_gcov[gb][5] = s8/K - az*az;
    }
}

// ===========================================================================
// select
// ===========================================================================
__global__ void __launch_bounds__(NT) select_kernel(const float* __restrict__ pts_all) {
    extern __shared__ float dyn[];
    float* sx = dyn;
    float* sy = sx + SVCAP;
    float* sz = sy + SVCAP;
    float* sd = sz + SVCAP;
    int*   si = (int*)(sd + SVCAP);
    unsigned* hist = (unsigned*)(si + SVCAP);
    __shared__ SelSh sh;

    const int tid = threadIdx.x;
    const int gb  = blockIdx.x;

    unsigned Sfull = d_nsv[gb];
    if (Sfull > SVCAP || Sfull < KNN) {
        if (tid == 0) d_flag[gb] = 2;
        return;
    }
    const int S = (int)Sfull;
    const int b = gb / NGRP, g = gb % NGRP;
    const int ci = g * STRIDE;
    const float* __restrict__ pts = pts_all + (size_t)b * NPTS * 3;
    const float qx = pts[3*ci], qy = pts[3*ci+1], qz = pts[3*ci+2];
    const float Ta = d_Ta[gb];

    for (int s = tid; s < S; s += NT) {
        float4 v = d_sv[gb][s];
        sx[s] = v.x; sy[s] = v.y; sz[s] = v.z;
        si[s] = __float_as_int(v.w);
        float dx = v.x - qx, dy = v.y - qy, dz = v.z - qz;
        sd[s] = fmaf(dx, dx, fmaf(dy, dy, dz*dz));
    }
    __syncthreads();

    // ---- pass 1 (survivors = ALL points < Ta, so exact) ----
    if (!select_topk(sd, si, hist, &sh, S, tid)) {
        if (tid == 0) d_flag[gb] = 2;
        return;
    }
    double vx = (tid < KNN) ? (double)sx[sh.order[tid]] : 0.0;
    double vy = (tid < KNN) ? (double)sy[sh.order[tid]] : 0.0;
    double vz = (tid < KNN) ? (double)sz[sh.order[tid]] : 0.0;
    double mx = tree_red(sh.red, tid, vx) / (double)KNN;
    double my = tree_red(sh.red, tid, vy) / (double)KNN;
    double mz = tree_red(sh.red, tid, vz) / (double)KNN;
    if (tid == 0) {
        d_gmean[gb][0] = mx; d_gmean[gb][1] = my; d_gmean[gb][2] = mz;
        float fmx = (float)mx, fmy = (float)my, fmz = (float)mz;
        d_meanf[gb][0] = fmx; d_meanf[gb][1] = fmy; d_meanf[gb][2] = fmz;
        double dxq = (double)fmx - (double)qx;
        double dyq = (double)fmy - (double)qy;
        double dzq = (double)fmz - (double)qz;
        sh.Dc = sqrt(dxq*dxq + dyq*dyq + dzq*dzq);
        sh.q2s[0] = fmx; sh.q2s[1] = fmy; sh.q2s[2] = fmz;
    }
    __syncthreads();

    // ---- pass 2 attempt over survivors ----
    const float mxf = sh.q2s[0], myf = sh.q2s[1], mzf = sh.q2s[2];
    __syncthreads();
    for (int s = tid; s < S; s += NT) {
        float dx = sx[s]-mxf, dy = sy[s]-myf, dz = sz[s]-mzf;
        sd[s] = fmaf(dx, dx, fmaf(dy, dy, dz*dz));
    }
    __syncthreads();
    if (!select_topk(sd, si, hist, &sh, S, tid)) {
        if (tid == 0) d_flag[gb] = 2;
        return;
    }
    if (tid == 0) {
        float d100 = sd[sh.order[KNN-1]];
        double lhs = sh.Dc + sqrt((double)d100);
        if (lhs*lhs*(1.0 + 1e-4) < (double)Ta) {
            sh.bflag = 0;
        } else {
            sh.bflag = 1;
            d_flag[gb] = 1;
            d_T2[gb] = d100;
        }
    }
    __syncthreads();
    if (sh.bflag) return;

    cov_store(sx, sy, sz, &sh, tid, gb);
}

// ===========================================================================
// rescue scan + select (flag==1)
// ===========================================================================
__global__ void __launch_bounds__(NT) rescue_scan_kernel(const float* __restrict__ pts_all) {
    const int gb = blockIdx.x / PTC;
    if (d_flag[gb] != 1) return;
    const int pc = blockIdx.x % PTC;
    const int b = gb / NGRP;
    const float* __restrict__ pts = pts_all + (size_t)b * NPTS * 3;
    const float4* __restrict__ p4 = (const float4*)pts;
    const float mxf = d_meanf[gb][0], myf = d_meanf[gb][1], mzf = d_meanf[gb][2];
    const float T2 = d_T2[gb];

    const int q0 = pc * (CHUNK/4);
    for (int it = q0 + threadIdx.x; it < q0 + CHUNK/4; it += NT) {
        float4 A = p4[3*it+0];
        float4 B = p4[3*it+1];
        float4 C = p4[3*it+2];
        float xs[4] = {A.x, A.w, B.z, C.y};
        float ys[4] = {A.y, B.x, B.w, C.z};
        float zs[4] = {A.z, B.y, C.x, C.w};
        #pragma unroll
        for (int k = 0; k < 4; k++) {
            float dx = xs[k]-mxf, dy = ys[k]-myf, dz = zs[k]-mzf;
            float d2 = fmaf(dx, dx, fmaf(dy, dy, dz*dz));
            if (d2 <= T2) {
                unsigned s = atomicAdd(&d_nsv2[gb], 1u);
                if (s < RCAP)
                    d_sv2[gb][s] = make_float4(xs[k], ys[k], zs[k],
                                               __int_as_float(4*it + k));
            }
        }
    }
}

__global__ void __launch_bounds__(NT) rescue_select_kernel() {
    const int gb = blockIdx.x;
    if (d_flag[gb] != 1) return;

    extern __shared__ float dyn[];
    float* sx = dyn;
    float* sy = sx + RCAP;
    float* sz = sy + RCAP;
    float* sd = sz + RCAP;
    int*   si = (int*)(sd + RCAP);
    unsigned* hist = (unsigned*)(si + RCAP);
    __shared__ SelSh sh;

    const int tid = threadIdx.x;
    unsigned S2u = d_nsv2[gb];
    if (S2u > RCAP || S2u < KNN) {
        if (tid == 0) d_flag[gb] = 2;
        return;
    }
    const int S = (int)S2u;
    const float mxf = d_meanf[gb][0], myf = d_meanf[gb][1], mzf = d_meanf[gb][2];

    for (int s = tid; s < S; s += NT) {
        float4 v = d_sv2[gb][s];
        sx[s] = v.x; sy[s] = v.y; sz[s] = v.z;
        si[s] = __float_as_int(v.w);
        float dx = v.x - mxf, dy = v.y - myf, dz = v.z - mzf;
        sd[s] = fmaf(dx, dx, fmaf(dy, dy, dz*dz));
    }
    __syncthreads();
    if (!select_topk(sd, si, hist, &sh, S, tid)) {
        if (tid == 0) d_flag[gb] = 2;
        return;
    }
    cov_store(sx, sy, sz, &sh, tid, gb);
}

// ===========================================================================
// brute fallback (flag==2 only; should never fire)
// ===========================================================================
__global__ void __launch_bounds__(NT, 2) fb_kernel(const float* __restrict__ pts_all) {
    const int gb = blockIdx.x;
    if (d_flag[gb] != 2) return;

    extern __shared__ float dyn[];
    float* cX = dyn;
    float* cY = cX + FCAP;
    float* cZ = cY + FCAP;
    int*   cI = (int*)(cZ + FCAP);

    __shared__ unsigned hist[HB];
    __shared__ unsigned partial[NT];
    __shared__ float    subD[FSCAP];
    __shared__ int      subI[FSCAP];
    __shared__ int      subSlot[FSCAP];
    __shared__ int      order[KNN];
    __shared__ unsigned ncand, nsub;
    __shared__ int      pivotS;
    __shared__ float    bc[4];

    const int tid = threadIdx.x;
    const int b   = gb / NGRP;
    const int g   = gb % NGRP;
    const float* __restrict__ pts = pts_all + (size_t)b * NPTS * 3;
    const float4* __restrict__ p4 = (const float4*)pts;

    const int c0 = g * STRIDE;
    const float qx = pts[3*c0+0], qy = pts[3*c0+1], qz = pts[3*c0+2];

    for (int i = tid; i < HB; i += NT) hist[i] = 0u;
    __syncthreads();
    for (int it = tid; it < NPTS/4; it += NT) {
        float4 A = p4[3*it+0], B = p4[3*it+1], C = p4[3*it+2];
        float xs[4] = {A.x, A.w, B.z, C.y};
        float ys[4] = {A.y, B.x, B.w, C.z};
        float zs[4] = {A.z, B.y, C.x, C.w};
        #pragma unroll
        for (int k = 0; k < 4; k++) {
            float dx = xs[k]-qx, dy = ys[k]-qy, dz = zs[k]-qz;
            atomicAdd(&hist[d2bin(fmaf(dx, dx, fmaf(dy, dy, dz*dz)))], 1u);
        }
    }
    __syncthreads();
    {
        unsigned ps = 0;
        #pragma unroll
        for (int j = 0; j < HB/NT; j++) ps += hist[tid*(HB/NT) + j];
        partial[tid] = ps;
    }
    __syncthreads();
    if (tid == 0) {
        unsigned c = 0; int t = 0;
        while (c + partial[t] < KNN) { c += partial[t]; t++; }
        int bin = t * (HB/NT);
        while (c + hist[bin] < KNN) { c += hist[bin]; bin++; }
        pivotS = bin;
    }
    __syncthreads();
    const float edge1 = __uint_as_float(((unsigned)pivotS + 1u) << 21);

    if (tid == 0) ncand = 0u;
    __syncthreads();
    for (int it = tid; it < NPTS/4; it += NT) {
        float4 A = p4[3*it+0], B = p4[3*it+1], C = p4[3*it+2];
        float xs[4] = {A.x, A.w, B.z, C.y};
        float ys[4] = {A.y, B.x, B.w, C.z};
        float zs[4] = {A.z, B.y, C.x, C.w};
        #pragma unroll
        for (int k = 0; k < 4; k++) {
            float dx = xs[k]-qx, dy = ys[k]-qy, dz = zs[k]-qz;
            float d2 = fmaf(dx, dx, fmaf(dy, dy, dz*dz));
            if (d2 < edge1) {
                unsigned s = atomicAdd(&ncand, 1u);
                if (s < FSCAP) {
                    cX[s] = xs[k]; cY[s] = ys[k]; cZ[s] = zs[k];
                    subD[s] = d2; subI[s] = 4*it + k;
                }
            }
        }
    }
    __syncthreads();
    {
        int S = (int)min(ncand, (unsigned)FSCAP);
        for (int s = tid; s < S; s += NT) {
            float d = subD[s]; int id = subI[s];
            int rank = 0;
            for (int j = 0; j < S; j++) {
                float dj = subD[j];
                rank += (dj < d) || (dj == d && subI[j] < id);
            }
            if (rank < KNN) order[rank] = s;
        }
    }
    __syncthreads();
    if (tid == 0) {
        double sxa = 0.0, sya = 0.0, sza = 0.0;
        for (int r = 0; r < KNN; r++) {
            int s = order[r];
            sxa += (double)cX[s]; sya += (double)cY[s]; sza += (double)cZ[s];
        }
        double mx = sxa/(double)KNN, my = sya/(double)KNN, mz = sza/(double)KNN;
        d_gmean[gb][0] = mx; d_gmean[gb][1] = my; d_gmean[gb][2] = mz;
        double dxq = mx - (double)qx, dyq = my - (double)qy, dzq = mz - (double)qz;
        double D  = sqrt(dxq*dxq + dyq*dyq + dzq*dzq);
        double r1 = sqrt((double)edge1);
        double R  = 2.0*D + r1;
        bc[0] = (float)mx; bc[1] = (float)my; bc[2] = (float)mz;
        bc[3] = (float)(R*R) * 1.0002f;
    }
    __syncthreads();
    const float q2x = bc[0], q2y = bc[1], q2z = bc[2];
    const float T2  = bc[3];

    if (tid == 0) ncand = 0u;
    __syncthreads();
    for (int it = tid; it < NPTS/4; it += NT) {
        float4 A = p4[3*it+0], B = p4[3*it+1], C = p4[3*it+2];
        float xs[4] = {A.x, A.w, B.z, C.y};
        float ys[4] = {A.y, B.x, B.w, C.z};
        float zs[4] = {A.z, B.y, C.x, C.w};
        #pragma unroll
        for (int k = 0; k < 4; k++) {
            float dx = xs[k]-qx, dy = ys[k]-qy, dz = zs[k]-qz;
            float d2 = fmaf(dx, dx, fmaf(dy, dy, dz*dz));
            if (d2 < T2) {
                unsigned s = atomicAdd(&ncand, 1u);
                if (s < FCAP) {
                    cX[s] = xs[k]; cY[s] = ys[k]; cZ[s] = zs[k];
                    cI[s] = 4*it + k;
                }
            }
        }
    }
    __syncthreads();
    const int C2 = (int)min(ncand, (unsigned)FCAP);

    for (int i = tid; i < HB; i += NT) hist[i] = 0u;
    __syncthreads();
    for (int c = tid; c < C2; c += NT) {
        float dx = cX[c]-q2x, dy = cY[c]-q2y, dz = cZ[c]-q2z;
        atomicAdd(&hist[d2bin(fmaf(dx, dx, fmaf(dy, dy, dz*dz)))], 1u);
    }
    __syncthreads();
    {
        unsigned ps = 0;
        #pragma unroll
        for (int j = 0; j < HB/NT; j++) ps += hist[tid*(HB/NT) + j];
        partial[tid] = ps;
    }
    __syncthreads();
    if (tid == 0) {
        unsigned c = 0; int t = 0;
        while (c + partial[t] < KNN) { c += partial[t]; t++; }
        int bin = t * (HB/NT);
        while (c + hist[bin] < KNN) { c += hist[bin]; bin++; }
        pivotS = bin;
        nsub = 0u;
    }
    __syncthreads();
    const unsigned piv2 = (unsigned)pivotS;
    for (int c = tid; c < C2; c += NT) {
        float dx = cX[c]-q2x, dy = cY[c]-q2y, dz = cZ[c]-q2z;
        float d2 = fmaf(dx, dx, fmaf(dy, dy, dz*dz));
        if (d2bin(d2) <= piv2) {
            unsigned s = atomicAdd(&nsub, 1u);
            if (s < FSCAP) { subD[s] = d2; subI[s] = cI[c]; subSlot[s] = c; }
        }
    }
    __syncthreads();
    {
        int S = (int)min(nsub, (unsigned)FSCAP);
        for (int s = tid; s < S; s += NT) {
            float d = subD[s]; int id = subI[s];
            int rank = 0;
            for (int j = 0; j < S; j++) {
                float dj = subD[j];
                rank += (dj < d) || (dj == d && subI[j] < id);
            }
            if (rank < KNN) order[rank] = subSlot[s];
        }
    }
    __syncthreads();
    if (tid == 0) {
        double s0=0,s1=0,s2=0,s3=0,s4=0,s5=0,s6=0,s7=0,s8=0;
        for (int r = 0; r < KNN; r++) {
            int c = order[r];
            double X = (double)cX[c], Y = (double)cY[c], Z = (double)cZ[c];
            s0 += X; s1 += Y; s2 += Z;
            s3 += X*X; s4 += X*Y; s5 += X*Z;
            s6 += Y*Y; s7 += Y*Z; s8 += Z*Z;
        }
        const double K = (double)KNN;
        double mx = s0/K, my = s1/K, mz = s2/K;
        d_gcov[gb][0] = s3/K - mx*mx;
        d_gcov[gb][1] = s4/K - mx*my;
        d_gcov[gb][2] = s5/K - mx*mz;
        d_gcov[gb][3] = s6/K - my*my;
        d_gcov[gb][4] = s7/K - my*mz;
        d_gcov[gb][5] = s8/K - mz*mz;
    }
}

// ===========================================================================
// eig + out
// ===========================================================================
__global__ void eig_kernel() {
    if (threadIdx.x != 0) return;
    const int t = blockIdx.x;

    double a00 = d_gcov[t][0], a01 = d_gcov[t][1], a02 = d_gcov[t][2];
    double a11 = d_gcov[t][3], a12 = d_gcov[t][4], a22 = d_gcov[t][5];

    double q  = (a00 + a11 + a22) / 3.0;
    double p1 = a01*a01 + a02*a02 + a12*a12;
    double b00 = a00 - q, b11 = a11 - q, b22 = a22 - q;
    double p2 = b00*b00 + b11*b11 + b22*b22 + 2.0*p1;
    double l1, l2, l3;
    if (p2 < 1e-60) {
        l1 = l2 = l3 = q;
    } else {
        double p  = sqrt(p2 / 6.0);
        double ip = 1.0 / p;
        double c00 = b00*ip, c11 = b11*ip, c22 = b22*ip;
        double c01 = a01*ip, c02 = a02*ip, c12 = a12*ip;
        double detB = c00*(c11*c22 - c12*c12)
                    - c01*(c01*c22 - c12*c02)
                    + c02*(c01*c12 - c11*c02);
        double r = 0.5 * detB;
        r = fmin(1.0, fmax(-1.0, r));
        double phi = (double)acosf((float)r) * (1.0/3.0);
        l3 = q + 2.0*p*(double)cosf((float)phi);
        l1 = q + 2.0*p*(double)cosf((float)(phi + 2.0943951023931953));
        l2 = 3.0*q - l1 - l3;
    }
    double denom = l1 + l2 + l3 + 1e-9;
    d_fs[t] = (l3 - l2) / denom;

    double r0x = a00 - l3, r0y = a01,      r0z = a02;
    double r1x = a01,      r1y = a11 - l3, r1z = a12;
    double r2x = a02,      r2y = a12,      r2z = a22 - l3;
    double vax = r0y*r1z - r0z*r1y, vay = r0z*r1x - r0x*r1z, vaz = r0x*r1y - r0y*r1x;
    double vbx = r1y*r2z - r1z*r2y, vby = r1z*r2x - r1x*r2z, vbz = r1x*r2y - r1y*r2x;
    double vcx = r2y*r0z - r2z*r0y, vcy = r2z*r0x - r2x*r0z, vcz = r2x*r0y - r2y*r0x;
    double na = vax*vax + vay*vay + vaz*vaz;
    double nb = vbx*vbx + vby*vby + vbz*vbz;
    double nc = vcx*vcx + vcy*vcy + vcz*vcz;
    double vx, vy, vz, nn;
    if (na >= nb && na >= nc) { vx = vax; vy = vay; vz = vaz; nn = na; }
    else if (nb >= nc)        { vx = vbx; vy = vby; vz = vbz; nn = nb; }
    else                      { vx = vcx; vy = vcy; vz = vcz; nn = nc; }
    if (nn < 1e-300) { vx = 0.0; vy = 0.0; vz = 1.0; nn = 1.0; }
    double inn = rsqrt(nn);
    d_dirs[t][0] = (float)(vx * inn);
    d_dirs[t][1] = (float)(vy * inn);
    d_dirs[t][2] = (float)(vz * inn);
}

__global__ void __launch_bounds__(256) out_kernel(float* __restrict__ out) {
    __shared__ float  dirs[NGB][3];
    __shared__ float  gmf[NGB][3];
    __shared__ double redd[256];
    const int t = threadIdx.x;

    double fs = 0.0;
    if (t < NGB) {
        fs = d_fs[t];
        dirs[t][0] = d_dirs[t][0];
        dirs[t][1] = d_dirs[t][1];
        dirs[t][2] = d_dirs[t][2];
        gmf[t][0] = (float)d_gmean[t][0];
        gmf[t][1] = (float)d_gmean[t][1];
        gmf[t][2] = (float)d_gmean[t][2];
    }
    __syncthreads();

    double term = 0.0;
    if (t < NGB) {
        int b = t / NGRP, g = t % NGRP;
        float qx = gmf[t][0], qy = gmf[t][1], qz = gmf[t][2];
        float best = 3.4e38f; int bj = 0;
        for (int o = 0; o < NGRP; o++) {
            float dx = qx - gmf[b*NGRP+o][0];
            float dy = qy - gmf[b*NGRP+o][1];
            float dz = qz - gmf[b*NGRP+o][2];
            float dd = dx*dx + dy*dy + dz*dz;
            if (o == g) dd += 1e30f;
            if (dd < best) { best = dd; bj = o; }
        }
        int j = b*NGRP + bj;
        float cs = dirs[t][0]*dirs[j][0] + dirs[t][1]*dirs[j][1] + dirs[t][2]*dirs[j][2];
        term = 1.0 - (double)cs * (double)cs;
    }

    redd[t] = fs;
    __syncthreads();
    for (int s = 128; s > 0; s >>= 1) { if (t < s) redd[t] += redd[t+s]; __syncthreads(); }
    double sumfs = redd[0];
    __syncthreads();
    redd[t] = term;
    __syncthreads();
    for (int s = 128; s > 0; s >>= 1) { if (t < s) redd[t] += redd[t+s]; __syncthreads(); }
    double sumterm = redd[0];

    if (t == 0) out[0] = (float)(-sumfs / (double)NBATCH + sumterm / (double)NGB);
}

extern "C" void kernel_launch(void* const* d_in, const int* in_sizes, int n_in,
                              void* d_out, int out_size) {
    const float* pts = (const float*)d_in[0];
    float* out = (float*)d_out;
    cudaFuncSetAttribute(select_kernel, cudaFuncAttributeMaxDynamicSharedMemorySize, SEL_DYN);
    cudaFuncSetAttribute(rescue_select_kernel, cudaFuncAttributeMaxDynamicSharedMemorySize, RES_DYN);
    cudaFuncSetAttribute(fb_kernel, cudaFuncAttributeMaxDynamicSharedMemorySize, FB_DYN);
    prep_kernel<<<1, 256>>>(pts);
    zero_cnt_kernel<<<SNB, SCB>>>();
    hist_kernel<<<TOTPTS/256, 256>>>(pts);
    scanA_kernel<<<SNB, SCB>>>();
    scanB_kernel<<<1, 1024>>>();
    scanC_kernel<<<SNB, SCB>>>();
    scatter_kernel<<<TOTPTS/256, 256>>>(pts);
    gather_kernel<<<NGB, NT>>>(pts);
    select_kernel<<<NGB, NT, SEL_DYN>>>(pts);
    rescue_scan_kernel<<<NGB*PTC, NT>>>(pts);
    rescue_select_kernel<<<NGB, NT, RES_DYN>>>();
    fb_kernel<<<NGB, NT, FB_DYN>>>(pts);
    eig_kernel<<<NGB, 32>>>();
    out_kernel<<<1, 256>>>(out);
}

// round 7
// speedup vs baseline: 1.4377x; 1.4377x over previous
#include <cuda_runtime.h>
#include <math.h>

#define NBATCH 8
#define NPTS   131072
#define TOTPTS (NBATCH*NPTS)
#define NGRP   30
#define NGB    (NBATCH*NGRP)   // 240
#define KNN    100
#define STRIDE 4369            // 131072/30
#define HB     2048            // float-radix bins: bits(d2) >> 21
#define SVCAP  2048
#define RCAP   4096
#define SUBCAP 1024
#define PTC    8
#define CHUNK  (NPTS/PTC)
#define NT     256
#define MTGT   700.0f

// uniform grid: 32^3 per batch, cell = 0.375
#define GR     32
#define GCELLS (GR*GR*GR)        // 32768
#define NCELLS (NBATCH*GCELLS)   // 262144
#define GLOW   (-6.0f)
#define INVH   2.6666666666666667f
#define SCB    1024
#define SNB    (NCELLS/SCB)      // 256

// brute fallback caps — should never fire
#define FCAP   6144
#define FSCAP  512
#define FB_DYN (4*FCAP*4)

#define SEL_DYN ((5*SVCAP + HB)*4)
#define RES_DYN ((5*RCAP  + HB)*4)

// -------- static device scratch --------
__device__ float    d_Ta[NGB];
__device__ unsigned d_nsv[NGB];
__device__ unsigned d_nsv2[NGB];
__device__ int      d_flag[NGB];        // 0 ok, 1 rescue pass-2, 2 brute
__device__ float    d_T2[NGB];
__device__ float    d_meanf[NGB][3];
__device__ float4   d_sv[NGB][SVCAP];
__device__ float4   d_sv2[NGB][RCAP];
__device__ double   d_gmean[NGB][3];
__device__ double   d_gcov[NGB][6];
__device__ float    d_dirs[NGB][3];
__device__ double   d_fs[NGB];

__device__ unsigned d_cellcnt[NCELLS];
__device__ unsigned d_cellstart[NCELLS];
__device__ unsigned d_cellcur[NCELLS];
__device__ unsigned d_bsum[SNB];
__device__ float4   d_spts[TOTPTS];     // cell-sorted points (x,y,z,idx)

__device__ __forceinline__ unsigned d2bin(float d2) {
    return __float_as_uint(d2) >> 21;
}
__device__ __forceinline__ int cellco(float x) {
    int c = (int)floorf((x - GLOW) * INVH);
    return min(GR-1, max(0, c));
}

// ===========================================================================
// prep: per-group analytic radius with expected MTGT points inside.
// ===========================================================================
__global__ void prep_kernel(const float* __restrict__ pts_all) {
    int t = threadIdx.x;
    if (t >= NGB) return;
    d_nsv[t] = 0u;
    d_nsv2[t] = 0u;
    d_flag[t] = 0;
    int b = t / NGRP, g = t % NGRP;
    int ci = g * STRIDE;
    const float* pts = pts_all + (size_t)b * NPTS * 3;
    float qx = pts[3*ci], qy = pts[3*ci+1], qz = pts[3*ci+2];
    float rho = sqrtf(qx*qx + qy*qy + qz*qz);
    rho = fmaxf(rho, 0.02f);
    const float A = (float)NPTS * 0.3989422804014327f / rho;
    float cum = 0.0f;
    float ds = 0.015f;
    float s = 0.5f * ds;
    float r = 8.0f;
    for (int it = 0; it < 540; it++) {
        float em = expf(-0.5f*(s-rho)*(s-rho)) - expf(-0.5f*(s+rho)*(s+rho));
        cum += A * s * em * ds;
        if (cum >= MTGT) { r = s + 0.5f*ds; break; }
        s += ds;
    }
    d_Ta[t] = r * r;
}

// ===========================================================================
// grid build
// ===========================================================================
__global__ void zero_cnt_kernel() {
    d_cellcnt[blockIdx.x * SCB + threadIdx.x] = 0u;
}

__global__ void hist_kernel(const float* __restrict__ pts_all) {
    int i = blockIdx.x * blockDim.x + threadIdx.x;
    const float* p = pts_all + 3u * (unsigned)i;
    int cx = cellco(p[0]), cy = cellco(p[1]), cz = cellco(p[2]);
    int b = i >> 17;
    int cell = ((b*GR + cz)*GR + cy)*GR + cx;
    atomicAdd(&d_cellcnt[cell], 1u);
}

__global__ void scanA_kernel() {
    __shared__ unsigned sh[SCB];
    int t = threadIdx.x;
    sh[t] = d_cellcnt[blockIdx.x * SCB + t];
    __syncthreads();
    for (int s = SCB/2; s > 0; s >>= 1) {
        if (t < s) sh[t] += sh[t+s];
        __syncthreads();
    }
    if (t == 0) d_bsum[blockIdx.x] = sh[0];
}

__global__ void scanB_kernel() {
    __shared__ unsigned sh[SNB];
    int t = threadIdx.x;   // SNB threads
    unsigned v = d_bsum[t];
    sh[t] = v; __syncthreads();
    for (int off = 1; off < SNB; off <<= 1) {
        unsigned u = sh[t];
        if (t >= off) u += sh[t - off];
        __syncthreads();
        sh[t] = u;
        __syncthreads();
    }
    d_bsum[t] = sh[t] - v;   // exclusive
}

__global__ void scanC_kernel() {
    __shared__ unsigned sh[SCB];
    int t = threadIdx.x;
    unsigned base = blockIdx.x * SCB + t;
    unsigned v = d_cellcnt[base];
    sh[t] = v; __syncthreads();
    for (int off = 1; off < SCB; off <<= 1) {
        unsigned u = sh[t];
        if (t >= off) u += sh[t - off];
        __syncthreads();
        sh[t] = u;
        __syncthreads();
    }
    unsigned st = d_bsum[blockIdx.x] + sh[t] - v;
    d_cellstart[base] = st;
    d_cellcur[base]  = st;
}

__global__ void scatter_kernel(const float* __restrict__ pts_all) {
    int i = blockIdx.x * blockDim.x + threadIdx.x;
    const float* p = pts_all + 3u * (unsigned)i;
    float px = p[0], py = p[1], pz = p[2];
    int cx = cellco(px), cy = cellco(py), cz = cellco(pz);
    int b = i >> 17;
    int cell = ((b*GR + cz)*GR + cy)*GR + cx;
    unsigned pos = atomicAdd(&d_cellcur[cell], 1u);
    d_spts[pos] = make_float4(px, py, pz, __int_as_float(i & (NPTS-1)));
}

// ===========================================================================
// gather: per group, span-based walk of the Ta-ball AABB over sorted points.
// x is the fastest grid dim, so cells [xlo..xhi] of one (z,y) row are one
// contiguous range of d_spts — fully coalesced, all threads active.
// Survivor set identical to a full Ta-scan (same d2 < Ta predicate).
// ===========================================================================
__global__ void __launch_bounds__(NT) gather_kernel(const float* __restrict__ pts_all) {
    const int gb = blockIdx.x;
    const int b = gb / NGRP, g = gb % NGRP;
    const float* __restrict__ pts = pts_all + (size_t)b * NPTS * 3;
    const int ci = g * STRIDE;
    const float qx = pts[3*ci], qy = pts[3*ci+1], qz = pts[3*ci+2];
    const float Ta = d_Ta[gb];
    const float r  = sqrtf(Ta) * 1.00001f;

    const int xlo = cellco(qx - r), xhi = cellco(qx + r);
    const int ylo = cellco(qy - r), yhi = cellco(qy + r);
    const int zlo = cellco(qz - r), zhi = cellco(qz + r);
    const int ny = yhi - ylo + 1;
    const int nz = zhi - zlo + 1;
    const int nspan = ny * nz;

    for (int sp = 0; sp < nspan; sp++) {
        int cy = ylo + sp % ny;
        int cz = zlo + sp / ny;
        int crow = ((b*GR + cz)*GR + cy)*GR;
        unsigned st = d_cellstart[crow + xlo];
        unsigned en = d_cellstart[crow + xhi] + d_cellcnt[crow + xhi];
        for (unsigned j = st + threadIdx.x; j < en; j += NT) {
            float4 p = d_spts[j];
            float dx = p.x-qx, dy = p.y-qy, dz = p.z-qz;
            float d2 = fmaf(dx, dx, fmaf(dy, dy, dz*dz));
            if (d2 < Ta) {
                unsigned s = atomicAdd(&d_nsv[gb], 1u);
                if (s < SVCAP) d_sv[gb][s] = p;
            }
        }
    }
}

// ===========================================================================
// shared selection machinery
// ===========================================================================
struct SelSh {
    unsigned partial[NT];
    int      subSlot[SUBCAP];
    int      order[KNN];
    double   red[NT];
    float    q2s[4];
    double   Dc;
    unsigned nsub;
    int      pivotS;
    int      bflag;
};

__device__ __forceinline__ double tree_red(double* red, int tid, double v) {
    red[tid] = v;
    __syncthreads();
    #pragma unroll
    for (int s = NT/2; s > 0; s >>= 1) {
        if (tid < s) red[tid] += red[tid + s];
        __syncthreads();
    }
    double r = red[0];
    __syncthreads();
    return r;
}

__device__ __forceinline__ bool select_topk(const float* sd, const int* si,
                                            unsigned* hist, SelSh* sh,
                                            int S, int tid) {
    for (int i = tid; i < HB; i += NT) hist[i] = 0u;
    if (tid == 0) sh->nsub = 0u;
    __syncthreads();
    for (int s = tid; s < S; s += NT) atomicAdd(&hist[d2bin(sd[s])], 1u);
    __syncthreads();
    {
        unsigned ps = 0;
        #pragma unroll
        for (int j = 0; j < HB/NT; j++) ps += hist[tid*(HB/NT) + j];
        sh->partial[tid] = ps;
    }
    __syncthreads();
    if (tid == 0) {
        unsigned c = 0; int t = 0;
        while (c + sh->partial[t] < KNN) { c += sh->partial[t]; t++; }
        int bin = t * (HB/NT);
        while (c + hist[bin] < KNN) { c += hist[bin]; bin++; }
        sh->pivotS = bin;
    }
    __syncthreads();
    const unsigned piv = (unsigned)sh->pivotS;
    for (int s = tid; s < S; s += NT) {
        if (d2bin(sd[s]) <= piv) {
            unsigned u = atomicAdd(&sh->nsub, 1u);
            if (u < SUBCAP) sh->subSlot[u] = s;
        }
    }
    __syncthreads();
    if (sh->nsub > SUBCAP) return false;
    const int U = (int)sh->nsub;
    for (int u = tid; u < U; u += NT) {
        int slot = sh->subSlot[u];
        float d = sd[slot]; int id = si[slot];
        int rank = 0;
        for (int v = 0; v < U; v++) {
            int s2 = sh->subSlot[v];
            float dv = sd[s2];
            rank += (dv < d) || (dv == d && si[s2] < id);
        }
        if (rank < KNN) sh->order[rank] = slot;
    }
    __syncthreads();
    return true;
}

__device__ __forceinline__ void cov_store(const float* sx, const float* sy,
                                          const float* sz, SelSh* sh,
                                          int tid, int gb) {
    double X = (tid < KNN) ? (double)sx[sh->order[tid]] : 0.0;
    double Y = (tid < KNN) ? (double)sy[sh->order[tid]] : 0.0;
    double Z = (tid < KNN) ? (double)sz[sh->order[tid]] : 0.0;
    double s0 = tree_red(sh->red, tid, X);
    double s1 = tree_red(sh->red, tid, Y);
    double s2 = tree_red(sh->red, tid, Z);
    double s3 = tree_red(sh->red, tid, X*X);
    double s4 = tree_red(sh->red, tid, X*Y);
    double s5 = tree_red(sh->red, tid, X*Z);
    double s6 = tree_red(sh->red, tid, Y*Y);
    double s7 = tree_red(sh->red, tid, Y*Z);
    double s8 = tree_red(sh->red, tid, Z*Z);
    if (tid == 0) {
        const double K = (double)KNN;
        double ax = s0/K, ay = s1/K, az = s2/K;
        d_gcov[gb][0] = s3/K - ax*ax;
        d_gcov[gb][1] = s4/K - ax*ay;
        d_gcov[gb][2] = s5/K - ax*az;
        d_gcov[gb][3] = s6/K - ay*ay;
        d_gcov[gb][4] = s7/K - ay*az;
        d_gcov[gb][5] = s8/K - az*az;
    }
}

// ===========================================================================
// select
// ===========================================================================
__global__ void __launch_bounds__(NT) select_kernel(const float* __restrict__ pts_all) {
    extern __shared__ float dyn[];
    float* sx = dyn;
    float* sy = sx + SVCAP;
    float* sz = sy + SVCAP;
    float* sd = sz + SVCAP;
    int*   si = (int*)(sd + SVCAP);
    unsigned* hist = (unsigned*)(si + SVCAP);
    __shared__ SelSh sh;

    const int tid = threadIdx.x;
    const int gb  = blockIdx.x;

    unsigned Sfull = d_nsv[gb];
    if (Sfull > SVCAP || Sfull < KNN) {
        if (tid == 0) d_flag[gb] = 2;
        return;
    }
    const int S = (int)Sfull;
    const int b = gb / NGRP, g = gb % NGRP;
    const int ci = g * STRIDE;
    const float* __restrict__ pts = pts_all + (size_t)b * NPTS * 3;
    const float qx = pts[3*ci], qy = pts[3*ci+1], qz = pts[3*ci+2];
    const float Ta = d_Ta[gb];

    for (int s = tid; s < S; s += NT) {
        float4 v = d_sv[gb][s];
        sx[s] = v.x; sy[s] = v.y; sz[s] = v.z;
        si[s] = __float_as_int(v.w);
        float dx = v.x - qx, dy = v.y - qy, dz = v.z - qz;
        sd[s] = fmaf(dx, dx, fmaf(dy, dy, dz*dz));
    }
    __syncthreads();

    // ---- pass 1 (survivors = ALL points < Ta, so exact) ----
    if (!select_topk(sd, si, hist, &sh, S, tid)) {
        if (tid == 0) d_flag[gb] = 2;
        return;
    }
    double vx = (tid < KNN) ? (double)sx[sh.order[tid]] : 0.0;
    double vy = (tid < KNN) ? (double)sy[sh.order[tid]] : 0.0;
    double vz = (tid < KNN) ? (double)sz[sh.order[tid]] : 0.0;
    double mx = tree_red(sh.red, tid, vx) / (double)KNN;
    double my = tree_red(sh.red, tid, vy) / (double)KNN;
    double mz = tree_red(sh.red, tid, vz) / (double)KNN;
    if (tid == 0) {
        d_gmean[gb][0] = mx; d_gmean[gb][1] = my; d_gmean[gb][2] = mz;
        float fmx = (float)mx, fmy = (float)my, fmz = (float)mz;
        d_meanf[gb][0] = fmx; d_meanf[gb][1] = fmy; d_meanf[gb][2] = fmz;
        double dxq = (double)fmx - (double)qx;
        double dyq = (double)fmy - (double)qy;
        double dzq = (double)fmz - (double)qz;
        sh.Dc = sqrt(dxq*dxq + dyq*dyq + dzq*dzq);
        sh.q2s[0] = fmx; sh.q2s[1] = fmy; sh.q2s[2] = fmz;
    }
    __syncthreads();

    // ---- pass 2 attempt over survivors ----
    const float mxf = sh.q2s[0], myf = sh.q2s[1], mzf = sh.q2s[2];
    __syncthreads();
    for (int s = tid; s < S; s += NT) {
        float dx = sx[s]-mxf, dy = sy[s]-myf, dz = sz[s]-mzf;
        sd[s] = fmaf(dx, dx, fmaf(dy, dy, dz*dz));
    }
    __syncthreads();
    if (!select_topk(sd, si, hist, &sh, S, tid)) {
        if (tid == 0) d_flag[gb] = 2;
        return;
    }
    if (tid == 0) {
        float d100 = sd[sh.order[KNN-1]];
        double lhs = sh.Dc + sqrt((double)d100);
        if (lhs*lhs*(1.0 + 1e-4) < (double)Ta) {
            sh.bflag = 0;
        } else {
            sh.bflag = 1;
            d_flag[gb] = 1;
            d_T2[gb] = d100;
        }
    }
    __syncthreads();
    if (sh.bflag) return;

    cov_store(sx, sy, sz, &sh, tid, gb);
}

// ===========================================================================
// rescue scan + select (flag==1)
// ===========================================================================
__global__ void __launch_bounds__(NT) rescue_scan_kernel(const float* __restrict__ pts_all) {
    const int gb = blockIdx.x / PTC;
    if (d_flag[gb] != 1) return;
    const int pc = blockIdx.x % PTC;
    const int b = gb / NGRP;
    const float* __restrict__ pts = pts_all + (size_t)b * NPTS * 3;
    const float4* __restrict__ p4 = (const float4*)pts;
    const float mxf = d_meanf[gb][0], myf = d_meanf[gb][1], mzf = d_meanf[gb][2];
    const float T2 = d_T2[gb];

    const int q0 = pc * (CHUNK/4);
    for (int it = q0 + threadIdx.x; it < q0 + CHUNK/4; it += NT) {
        float4 A = p4[3*it+0];
        float4 B = p4[3*it+1];
        float4 C = p4[3*it+2];
        float xs[4] = {A.x, A.w, B.z, C.y};
        float ys[4] = {A.y, B.x, B.w, C.z};
        float zs[4] = {A.z, B.y, C.x, C.w};
        #pragma unroll
        for (int k = 0; k < 4; k++) {
            float dx = xs[k]-mxf, dy = ys[k]-myf, dz = zs[k]-mzf;
            float d2 = fmaf(dx, dx, fmaf(dy, dy, dz*dz));
            if (d2 <= T2) {
                unsigned s = atomicAdd(&d_nsv2[gb], 1u);
                if (s < RCAP)
                    d_sv2[gb][s] = make_float4(xs[k], ys[k], zs[k],
                                               __int_as_float(4*it + k));
            }
        }
    }
}

__global__ void __launch_bounds__(NT) rescue_select_kernel() {
    const int gb = blockIdx.x;
    if (d_flag[gb] != 1) return;

    extern __shared__ float dyn[];
    float* sx = dyn;
    float* sy = sx + RCAP;
    float* sz = sy + RCAP;
    float* sd = sz + RCAP;
    int*   si = (int*)(sd + RCAP);
    unsigned* hist = (unsigned*)(si + RCAP);
    __shared__ SelSh sh;

    const int tid = threadIdx.x;
    unsigned S2u = d_nsv2[gb];
    if (S2u > RCAP || S2u < KNN) {
        if (tid == 0) d_flag[gb] = 2;
        return;
    }
    const int S = (int)S2u;
    const float mxf = d_meanf[gb][0], myf = d_meanf[gb][1], mzf = d_meanf[gb][2];

    for (int s = tid; s < S; s += NT) {
        float4 v = d_sv2[gb][s];
        sx[s] = v.x; sy[s] = v.y; sz[s] = v.z;
        si[s] = __float_as_int(v.w);
        float dx = v.x - mxf, dy = v.y - myf, dz = v.z - mzf;
        sd[s] = fmaf(dx, dx, fmaf(dy, dy, dz*dz));
    }
    __syncthreads();
    if (!select_topk(sd, si, hist, &sh, S, tid)) {
        if (tid == 0) d_flag[gb] = 2;
        return;
    }
    cov_store(sx, sy, sz, &sh, tid, gb);
}

// ===========================================================================
// brute fallback (flag==2 only; should never fire)
// ===========================================================================
__global__ void __launch_bounds__(NT, 2) fb_kernel(const float* __restrict__ pts_all) {
    const int gb = blockIdx.x;
    if (d_flag[gb] != 2) return;

    extern __shared__ float dyn[];
    float* cX = dyn;
    float* cY = cX + FCAP;
    float* cZ = cY + FCAP;
    int*   cI = (int*)(cZ + FCAP);

    __shared__ unsigned hist[HB];
    __shared__ unsigned partial[NT];
    __shared__ float    subD[FSCAP];
    __shared__ int      subI[FSCAP];
    __shared__ int      subSlot[FSCAP];
    __shared__ int      order[KNN];
    __shared__ unsigned ncand, nsub;
    __shared__ int      pivotS;
    __shared__ float    bc[4];

    const int tid = threadIdx.x;
    const int b   = gb / NGRP;
    const int g   = gb % NGRP;
    const float* __restrict__ pts = pts_all + (size_t)b * NPTS * 3;
    const float4* __restrict__ p4 = (const float4*)pts;

    const int c0 = g * STRIDE;
    const float qx = pts[3*c0+0], qy = pts[3*c0+1], qz = pts[3*c0+2];

    for (int i = tid; i < HB; i += NT) hist[i] = 0u;
    __syncthreads();
    for (int it = tid; it < NPTS/4; it += NT) {
        float4 A = p4[3*it+0], B = p4[3*it+1], C = p4[3*it+2];
        float xs[4] = {A.x, A.w, B.z, C.y};
        float ys[4] = {A.y, B.x, B.w, C.z};
        float zs[4] = {A.z, B.y, C.x, C.w};
        #pragma unroll
        for (int k = 0; k < 4; k++) {
            float dx = xs[k]-qx, dy = ys[k]-qy, dz = zs[k]-qz;
            atomicAdd(&hist[d2bin(fmaf(dx, dx, fmaf(dy, dy, dz*dz)))], 1u);
        }
    }
    __syncthreads();
    {
        unsigned ps = 0;
        #pragma unroll
        for (int j = 0; j < HB/NT; j++) ps += hist[tid*(HB/NT) + j];
        partial[tid] = ps;
    }
    __syncthreads();
    if (tid == 0) {
        unsigned c = 0; int t = 0;
        while (c + partial[t] < KNN) { c += partial[t]; t++; }
        int bin = t * (HB/NT);
        while (c + hist[bin] < KNN) { c += hist[bin]; bin++; }
        pivotS = bin;
    }
    __syncthreads();
    const float edge1 = __uint_as_float(((unsigned)pivotS + 1u) << 21);

    if (tid == 0) ncand = 0u;
    __syncthreads();
    for (int it = tid; it < NPTS/4; it += NT) {
        float4 A = p4[3*it+0], B = p4[3*it+1], C = p4[3*it+2];
        float xs[4] = {A.x, A.w, B.z, C.y};
        float ys[4] = {A.y, B.x, B.w, C.z};
        float zs[4] = {A.z, B.y, C.x, C.w};
        #pragma unroll
        for (int k = 0; k < 4; k++) {
            float dx = xs[k]-qx, dy = ys[k]-qy, dz = zs[k]-qz;
            float d2 = fmaf(dx, dx, fmaf(dy, dy, dz*dz));
            if (d2 < edge1) {
                unsigned s = atomicAdd(&ncand, 1u);
                if (s < FSCAP) {
                    cX[s] = xs[k]; cY[s] = ys[k]; cZ[s] = zs[k];
                    subD[s] = d2; subI[s] = 4*it + k;
                }
            }
        }
    }
    __syncthreads();
    {
        int S = (int)min(ncand, (unsigned)FSCAP);
        for (int s = tid; s < S; s += NT) {
            float d = subD[s]; int id = subI[s];
            int rank = 0;
            for (int j = 0; j < S; j++) {
                float dj = subD[j];
                rank += (dj < d) || (dj == d && subI[j] < id);
            }
            if (rank < KNN) order[rank] = s;
        }
    }
    __syncthreads();
    if (tid == 0) {
        double sxa = 0.0, sya = 0.0, sza = 0.0;
        for (int r = 0; r < KNN; r++) {
            int s = order[r];
            sxa += (double)cX[s]; sya += (double)cY[s]; sza += (double)cZ[s];
        }
        double mx = sxa/(double)KNN, my = sya/(double)KNN, mz = sza/(double)KNN;
        d_gmean[gb][0] = mx; d_gmean[gb][1] = my; d_gmean[gb][2] = mz;
        double dxq = mx - (double)qx, dyq = my - (double)qy, dzq = mz - (double)qz;
        double D  = sqrt(dxq*dxq + dyq*dyq + dzq*dzq);
        double r1 = sqrt((double)edge1);
        double R  = 2.0*D + r1;
        bc[0] = (float)mx; bc[1] = (float)my; bc[2] = (float)mz;
        bc[3] = (float)(R*R) * 1.0002f;
    }
    __syncthreads();
    const float q2x = bc[0], q2y = bc[1], q2z = bc[2];
    const float T2  = bc[3];

    if (tid == 0) ncand = 0u;
    __syncthreads();
    for (int it = tid; it < NPTS/4; it += NT) {
        float4 A = p4[3*it+0], B = p4[3*it+1], C = p4[3*it+2];
        float xs[4] = {A.x, A.w, B.z, C.y};
        float ys[4] = {A.y, B.x, B.w, C.z};
        float zs[4] = {A.z, B.y, C.x, C.w};
        #pragma unroll
        for (int k = 0; k < 4; k++) {
            float dx = xs[k]-qx, dy = ys[k]-qy, dz = zs[k]-qz;
            float d2 = fmaf(dx, dx, fmaf(dy, dy, dz*dz));
            if (d2 < T2) {
                unsigned s = atomicAdd(&ncand, 1u);
                if (s < FCAP) {
                    cX[s] = xs[k]; cY[s] = ys[k]; cZ[s] = zs[k];
                    cI[s] = 4*it + k;
                }
            }
        }
    }
    __syncthreads();
    const int C2 = (int)min(ncand, (unsigned)FCAP);

    for (int i = tid; i < HB; i += NT) hist[i] = 0u;
    __syncthreads();
    for (int c = tid; c < C2; c += NT) {
        float dx = cX[c]-q2x, dy = cY[c]-q2y, dz = cZ[c]-q2z;
        atomicAdd(&hist[d2bin(fmaf(dx, dx, fmaf(dy, dy, dz*dz)))], 1u);
    }
    __syncthreads();
    {
        unsigned ps = 0;
        #pragma unroll
        for (int j = 0; j < HB/NT; j++) ps += hist[tid*(HB/NT) + j];
        partial[tid] = ps;
    }
    __syncthreads();
    if (tid == 0) {
        unsigned c = 0; int t = 0;
        while (c + partial[t] < KNN) { c += partial[t]; t++; }
        int bin = t * (HB/NT);
        while (c + hist[bin] < KNN) { c += hist[bin]; bin++; }
        pivotS = bin;
        nsub = 0u;
    }
    __syncthreads();
    const unsigned piv2 = (unsigned)pivotS;
    for (int c = tid; c < C2; c += NT) {
        float dx = cX[c]-q2x, dy = cY[c]-q2y, dz = cZ[c]-q2z;
        float d2 = fmaf(dx, dx, fmaf(dy, dy, dz*dz));
        if (d2bin(d2) <= piv2) {
            unsigned s = atomicAdd(&nsub, 1u);
            if (s < FSCAP) { subD[s] = d2; subI[s] = cI[c]; subSlot[s] = c; }
        }
    }
    __syncthreads();
    {
        int S = (int)min(nsub, (unsigned)FSCAP);
        for (int s = tid; s < S; s += NT) {
            float d = subD[s]; int id = subI[s];
            int rank = 0;
            for (int j = 0; j < S; j++) {
                float dj = subD[j];
                rank += (dj < d) || (dj == d && subI[j] < id);
            }
            if (rank < KNN) order[rank] = subSlot[s];
        }
    }
    __syncthreads();
    if (tid == 0) {
        double s0=0,s1=0,s2=0,s3=0,s4=0,s5=0,s6=0,s7=0,s8=0;
        for (int r = 0; r < KNN; r++) {
            int c = order[r];
            double X = (double)cX[c], Y = (double)cY[c], Z = (double)cZ[c];
            s0 += X; s1 += Y; s2 += Z;
            s3 += X*X; s4 += X*Y; s5 += X*Z;
            s6 += Y*Y; s7 += Y*Z; s8 += Z*Z;
        }
        const double K = (double)KNN;
        double mx = s0/K, my = s1/K, mz = s2/K;
        d_gcov[gb][0] = s3/K - mx*mx;
        d_gcov[gb][1] = s4/K - mx*my;
        d_gcov[gb][2] = s5/K - mx*mz;
        d_gcov[gb][3] = s6/K - my*my;
        d_gcov[gb][4] = s7/K - my*mz;
        d_gcov[gb][5] = s8/K - mz*mz;
    }
}

// ===========================================================================
// eig + out
// ===========================================================================
__global__ void eig_kernel() {
    if (threadIdx.x != 0) return;
    const int t = blockIdx.x;

    double a00 = d_gcov[t][0], a01 = d_gcov[t][1], a02 = d_gcov[t][2];
    double a11 = d_gcov[t][3], a12 = d_gcov[t][4], a22 = d_gcov[t][5];

    double q  = (a00 + a11 + a22) / 3.0;
    double p1 = a01*a01 + a02*a02 + a12*a12;
    double b00 = a00 - q, b11 = a11 - q, b22 = a22 - q;
    double p2 = b00*b00 + b11*b11 + b22*b22 + 2.0*p1;
    double l1, l2, l3;
    if (p2 < 1e-60) {
        l1 = l2 = l3 = q;
    } else {
        double p  = sqrt(p2 / 6.0);
        double ip = 1.0 / p;
        double c00 = b00*ip, c11 = b11*ip, c22 = b22*ip;
        double c01 = a01*ip, c02 = a02*ip, c12 = a12*ip;
        double detB = c00*(c11*c22 - c12*c12)
                    - c01*(c01*c22 - c12*c02)
                    + c02*(c01*c12 - c11*c02);
        double r = 0.5 * detB;
        r = fmin(1.0, fmax(-1.0, r));
        double phi = (double)acosf((float)r) * (1.0/3.0);
        l3 = q + 2.0*p*(double)cosf((float)phi);
        l1 = q + 2.0*p*(double)cosf((float)(phi + 2.0943951023931953));
        l2 = 3.0*q - l1 - l3;
    }
    double denom = l1 + l2 + l3 + 1e-9;
    d_fs[t] = (l3 - l2) / denom;

    double r0x = a00 - l3, r0y = a01,      r0z = a02;
    double r1x = a01,      r1y = a11 - l3, r1z = a12;
    double r2x = a02,      r2y = a12,      r2z = a22 - l3;
    double vax = r0y*r1z - r0z*r1y, vay = r0z*r1x - r0x*r1z, vaz = r0x*r1y - r0y*r1x;
    double vbx = r1y*r2z - r1z*r2y, vby = r1z*r2x - r1x*r2z, vbz = r1x*r2y - r1y*r2x;
    double vcx = r2y*r0z - r2z*r0y, vcy = r2z*r0x - r2x*r0z, vcz = r2x*r0y - r2y*r0x;
    double na = vax*vax + vay*vay + vaz*vaz;
    double nb = vbx*vbx + vby*vby + vbz*vbz;
    double nc = vcx*vcx + vcy*vcy + vcz*vcz;
    double vx, vy, vz, nn;
    if (na >= nb && na >= nc) { vx = vax; vy = vay; vz = vaz; nn = na; }
    else if (nb >= nc)        { vx = vbx; vy = vby; vz = vbz; nn = nb; }
    else                      { vx = vcx; vy = vcy; vz = vcz; nn = nc; }
    if (nn < 1e-300) { vx = 0.0; vy = 0.0; vz = 1.0; nn = 1.0; }
    double inn = rsqrt(nn);
    d_dirs[t][0] = (float)(vx * inn);
    d_dirs[t][1] = (float)(vy * inn);
    d_dirs[t][2] = (float)(vz * inn);
}

__global__ void __launch_bounds__(256) out_kernel(float* __restrict__ out) {
    __shared__ float  dirs[NGB][3];
    __shared__ float  gmf[NGB][3];
    __shared__ double redd[256];
    const int t = threadIdx.x;

    double fs = 0.0;
    if (t < NGB) {
        fs = d_fs[t];
        dirs[t][0] = d_dirs[t][0];
        dirs[t][1] = d_dirs[t][1];
        dirs[t][2] = d_dirs[t][2];
        gmf[t][0] = (float)d_gmean[t][0];
        gmf[t][1] = (float)d_gmean[t][1];
        gmf[t][2] = (float)d_gmean[t][2];
    }
    __syncthreads();

    double term = 0.0;
    if (t < NGB) {
        int b = t / NGRP, g = t % NGRP;
        float qx = gmf[t][0], qy = gmf[t][1], qz = gmf[t][2];
        float best = 3.4e38f; int bj = 0;
        for (int o = 0; o < NGRP; o++) {
            float dx = qx - gmf[b*NGRP+o][0];
            float dy = qy - gmf[b*NGRP+o][1];
            float dz = qz - gmf[b*NGRP+o][2];
            float dd = dx*dx + dy*dy + dz*dz;
            if (o == g) dd += 1e30f;
            if (dd < best) { best = dd; bj = o; }
        }
        int j = b*NGRP + bj;
        float cs = dirs[t][0]*dirs[j][0] + dirs[t][1]*dirs[j][1] + dirs[t][2]*dirs[j][2];
        term = 1.0 - (double)cs * (double)cs;
    }

    redd[t] = fs;
    __syncthreads();
    for (int s = 128; s > 0; s >>= 1) { if (t < s) redd[t] += redd[t+s]; __syncthreads(); }
    double sumfs = redd[0];
    __syncthreads();
    redd[t] = term;
    __syncthreads();
    for (int s = 128; s > 0; s >>= 1) { if (t < s) redd[t] += redd[t+s]; __syncthreads(); }
    double sumterm = redd[0];

    if (t == 0) out[0] = (float)(-sumfs / (double)NBATCH + sumterm / (double)NGB);
}

extern "C" void kernel_launch(void* const* d_in, const int* in_sizes, int n_in,
                              void* d_out, int out_size) {
    const float* pts = (const float*)d_in[0];
    float* out = (float*)d_out;
    cudaFuncSetAttribute(select_kernel, cudaFuncAttributeMaxDynamicSharedMemorySize, SEL_DYN);
    cudaFuncSetAttribute(rescue_select_kernel, cudaFuncAttributeMaxDynamicSharedMemorySize, RES_DYN);
    cudaFuncSetAttribute(fb_kernel, cudaFuncAttributeMaxDynamicSharedMemorySize, FB_DYN);
    prep_kernel<<<1, 256>>>(pts);
    zero_cnt_kernel<<<SNB, SCB>>>();
    hist_kernel<<<TOTPTS/256, 256>>>(pts);
    scanA_kernel<<<SNB, SCB>>>();
    scanB_kernel<<<1, SNB>>>();
    scanC_kernel<<<SNB, SCB>>>();
    scatter_kernel<<<TOTPTS/256, 256>>>(pts);
    gather_kernel<<<NGB, NT>>>(pts);
    select_kernel<<<NGB, NT, SEL_DYN>>>(pts);
    rescue_scan_kernel<<<NGB*PTC, NT>>>(pts);
    rescue_select_kernel<<<NGB, NT, RES_DYN>>>();
    fb_kernel<<<NGB, NT, FB_DYN>>>(pts);
    eig_kernel<<<NGB, 32>>>();
    out_kernel<<<1, 256>>>(out);
}

// round 8
// speedup vs baseline: 2.3995x; 1.6690x over previous
#include <cuda_runtime.h>
#include <math.h>

#define NBATCH 8
#define NPTS   131072
#define NGRP   30
#define NGB    (NBATCH*NGRP)   // 240
#define KNN    100
#define STRIDE 4369            // 131072/30
#define HB     2048            // float-radix bins: bits(d2) >> 21
#define GPT    6               // groups per tile
#define GT     5               // tiles
#define PTC    8               // point chunks
#define CHUNK  (NPTS/PTC)      // 16384
#define NT     256
#define MTGT   700.0f

#define SEGCAP 256             // per-(group,chunk) survivor segment
#define SELCAP (PTC*SEGCAP)    // 2048 max total survivors
#define SUBCAP 1024
#define FCAP   6144            // fin candidate buffer

#define SEL_DYN ((5*SELCAP + HB)*4)
#define FIN_DYN ((5*FCAP  + HB)*4)

// -------- static device scratch --------
__device__ float    d_Ta[NGB];
__device__ unsigned d_segcnt[NGB][PTC];
__device__ float4   d_seg[NGB][PTC][SEGCAP];
__device__ int      d_flag[NGB];        // 0 ok, 1 rescue, 2 brute
__device__ float    d_T2[NGB];
__device__ float    d_meanf[NGB][3];
__device__ double   d_gmean[NGB][3];
__device__ double   d_gcov[NGB][6];
__device__ float    d_dirs[NGB][3];
__device__ double   d_fs[NGB];
__device__ unsigned d_ticket;

__device__ __forceinline__ unsigned d2bin(float d2) {
    return __float_as_uint(d2) >> 21;
}

// ===========================================================================
// K1: scan. Each block = (batch, 6-group tile, chunk). Computes its groups'
// radii via bisection on the closed-form distance CDF, then writes survivors
// (same diff-form d2 < Ta predicate as before) into private segments.
// ===========================================================================
__global__ void __launch_bounds__(NT) scan_kernel(const float* __restrict__ pts_all) {
    __shared__ float ta[GPT], qxs[GPT], qys[GPT], qzs[GPT];
    __shared__ unsigned scnt[GPT];
    const int bidx = blockIdx.x;
    const int pc = bidx % PTC;
    const int gt = (bidx / PTC) % GT;
    const int b  = bidx / (PTC * GT);
    const float* __restrict__ pts = pts_all + (size_t)b * NPTS * 3;
    const float4* __restrict__ p4 = (const float4*)pts;
    const int gbase = b * NGRP + gt * GPT;
    const int tid = threadIdx.x;

    if (tid < GPT) {
        int ci = (gt*GPT + tid) * STRIDE;
        float qx = pts[3*ci], qy = pts[3*ci+1], qz = pts[3*ci+2];
        qxs[tid] = qx; qys[tid] = qy; qzs[tid] = qz;
        float rho = fmaxf(sqrtf(qx*qx + qy*qy + qz*qz), 0.02f);
        const float tgt = MTGT / (float)NPTS;
        const float irho = 0.3989423f / rho;
        float lo = 0.01f, hi = 6.0f;
        #pragma unroll 1
        for (int it = 0; it < 40; it++) {
            float s = 0.5f*(lo + hi);
            float a = s - rho, c = s + rho;
            float F = 0.5f*erff(a*0.70710678f) + 0.5f*erff(c*0.70710678f)
                    - (expf(-0.5f*a*a) - expf(-0.5f*c*c)) * irho;
            if (F >= tgt) hi = s; else lo = s;
        }
        ta[tid] = hi * hi;
        d_Ta[gbase + tid] = hi * hi;      // duplicate identical writes OK
        scnt[tid] = 0u;
    }
    if (bidx == 0 && tid == 0) d_ticket = 0u;
    __syncthreads();

    float qx[GPT], qy[GPT], qz[GPT], tta[GPT];
    #pragma unroll
    for (int j = 0; j < GPT; j++) { qx[j]=qxs[j]; qy[j]=qys[j]; qz[j]=qzs[j]; tta[j]=ta[j]; }

    const int q0 = pc * (CHUNK/4);
    for (int it = q0 + tid; it < q0 + CHUNK/4; it += NT) {
        float4 A = p4[3*it+0];
        float4 B = p4[3*it+1];
        float4 C = p4[3*it+2];
        float xs[4] = {A.x, A.w, B.z, C.y};
        float ys[4] = {A.y, B.x, B.w, C.z};
        float zs[4] = {A.z, B.y, C.x, C.w};
        #pragma unroll
        for (int k = 0; k < 4; k++) {
            #pragma unroll
            for (int j = 0; j < GPT; j++) {
                float dx = xs[k]-qx[j], dy = ys[k]-qy[j], dz = zs[k]-qz[j];
                float d2 = fmaf(dx, dx, fmaf(dy, dy, dz*dz));
                if (d2 < tta[j]) {
                    unsigned s = atomicAdd(&scnt[j], 1u);
                    if (s < SEGCAP)
                        d_seg[gbase + j][pc][s] = make_float4(xs[k], ys[k], zs[k],
                                                              __int_as_float(4*it + k));
                }
            }
        }
    }
    __syncthreads();
    if (tid < GPT) d_segcnt[gbase + tid][pc] = scnt[tid];
}

// ===========================================================================
// shared selection machinery
// ===========================================================================
struct SelSh {
    unsigned partial[NT];
    int      subSlot[SUBCAP];
    int      order[KNN];
    double   red[NT];
    float    q2s[4];
    double   Dc;
    unsigned nsub;
    int      pivotS;
    int      bflag;
};

__device__ __forceinline__ double tree_red(double* red, int tid, double v) {
    red[tid] = v;
    __syncthreads();
    #pragma unroll
    for (int s = NT/2; s > 0; s >>= 1) {
        if (tid < s) red[tid] += red[tid + s];
        __syncthreads();
    }
    double r = red[0];
    __syncthreads();
    return r;
}

__device__ __forceinline__ bool select_topk(const float* sd, const int* si,
                                            unsigned* hist, SelSh* sh,
                                            int S, int tid) {
    for (int i = tid; i < HB; i += NT) hist[i] = 0u;
    if (tid == 0) sh->nsub = 0u;
    __syncthreads();
    for (int s = tid; s < S; s += NT) atomicAdd(&hist[d2bin(sd[s])], 1u);
    __syncthreads();
    {
        unsigned ps = 0;
        #pragma unroll
        for (int j = 0; j < HB/NT; j++) ps += hist[tid*(HB/NT) + j];
        sh->partial[tid] = ps;
    }
    __syncthreads();
    if (tid == 0) {
        unsigned c = 0; int t = 0;
        while (c + sh->partial[t] < KNN) { c += sh->partial[t]; t++; }
        int bin = t * (HB/NT);
        while (c + hist[bin] < KNN) { c += hist[bin]; bin++; }
        sh->pivotS = bin;
    }
    __syncthreads();
    const unsigned piv = (unsigned)sh->pivotS;
    for (int s = tid; s < S; s += NT) {
        if (d2bin(sd[s]) <= piv) {
            unsigned u = atomicAdd(&sh->nsub, 1u);
            if (u < SUBCAP) sh->subSlot[u] = s;
        }
    }
    __syncthreads();
    bool ok = (sh->nsub <= SUBCAP);
    const int U = (int)min(sh->nsub, (unsigned)SUBCAP);
    for (int u = tid; u < U; u += NT) {
        int slot = sh->subSlot[u];
        float d = sd[slot]; int id = si[slot];
        int rank = 0;
        for (int v = 0; v < U; v++) {
            int s2 = sh->subSlot[v];
            float dv = sd[s2];
            rank += (dv < d) || (dv == d && si[s2] < id);
        }
        if (rank < KNN) sh->order[rank] = slot;
    }
    __syncthreads();
    return ok;
}

__device__ __forceinline__ void cov_store(const float* sx, const float* sy,
                                          const float* sz, SelSh* sh,
                                          int tid, int gb) {
    double X = (tid < KNN) ? (double)sx[sh->order[tid]] : 0.0;
    double Y = (tid < KNN) ? (double)sy[sh->order[tid]] : 0.0;
    double Z = (tid < KNN) ? (double)sz[sh->order[tid]] : 0.0;
    double s0 = tree_red(sh->red, tid, X);
    double s1 = tree_red(sh->red, tid, Y);
    double s2 = tree_red(sh->red, tid, Z);
    double s3 = tree_red(sh->red, tid, X*X);
    double s4 = tree_red(sh->red, tid, X*Y);
    double s5 = tree_red(sh->red, tid, X*Z);
    double s6 = tree_red(sh->red, tid, Y*Y);
    double s7 = tree_red(sh->red, tid, Y*Z);
    double s8 = tree_red(sh->red, tid, Z*Z);
    if (tid == 0) {
        const double K = (double)KNN;
        double ax = s0/K, ay = s1/K, az = s2/K;
        d_gcov[gb][0] = s3/K - ax*ax;
        d_gcov[gb][1] = s4/K - ax*ay;
        d_gcov[gb][2] = s5/K - ax*az;
        d_gcov[gb][3] = s6/K - ay*ay;
        d_gcov[gb][4] = s7/K - ay*az;
        d_gcov[gb][5] = s8/K - az*az;
    }
}

// ===========================================================================
// K2: select. Reads segments; exact pass-1, pass-2 with containment test.
// Writes d_flag for EVERY group (0/1/2).
// ===========================================================================
__global__ void __launch_bounds__(NT) select_kernel(const float* __restrict__ pts_all) {
    extern __shared__ float dyn[];
    float* sx = dyn;
    float* sy = sx + SELCAP;
    float* sz = sy + SELCAP;
    float* sd = sz + SELCAP;
    int*   si = (int*)(sd + SELCAP);
    unsigned* hist = (unsigned*)(si + SELCAP);
    __shared__ SelSh sh;
    __shared__ unsigned offs[PTC+1];

    const int tid = threadIdx.x;
    const int gb  = blockIdx.x;

    if (tid == 0) {
        unsigned o = 0; int bad = 0;
        for (int pc = 0; pc < PTC; pc++) {
            unsigned c = d_segcnt[gb][pc];
            if (c > SEGCAP) bad = 1;
            offs[pc] = o; o += (c > SEGCAP ? SEGCAP : c);
        }
        offs[PTC] = o;
        sh.bflag = (bad || o < KNN) ? 2 : 0;
    }
    __syncthreads();
    if (sh.bflag) { if (tid == 0) d_flag[gb] = 2; return; }
    const int S = (int)offs[PTC];

    const int b = gb / NGRP, g = gb % NGRP;
    const int ci = g * STRIDE;
    const float* __restrict__ pts = pts_all + (size_t)b * NPTS * 3;
    const float qx = pts[3*ci], qy = pts[3*ci+1], qz = pts[3*ci+2];
    const float Ta = d_Ta[gb];

    for (int pc = 0; pc < PTC; pc++) {
        unsigned base = offs[pc], cnt = offs[pc+1] - offs[pc];
        for (unsigned u = tid; u < cnt; u += NT) {
            float4 v = d_seg[gb][pc][u];
            sx[base+u] = v.x; sy[base+u] = v.y; sz[base+u] = v.z;
            si[base+u] = __float_as_int(v.w);
        }
    }
    __syncthreads();
    for (int s = tid; s < S; s += NT) {
        float dx = sx[s]-qx, dy = sy[s]-qy, dz = sz[s]-qz;
        sd[s] = fmaf(dx, dx, fmaf(dy, dy, dz*dz));
    }
    __syncthreads();

    // ---- pass 1 (survivors = ALL points < Ta, exact) ----
    if (!select_topk(sd, si, hist, &sh, S, tid)) {
        if (tid == 0) d_flag[gb] = 2;
        return;
    }
    double vx = (tid < KNN) ? (double)sx[sh.order[tid]] : 0.0;
    double vy = (tid < KNN) ? (double)sy[sh.order[tid]] : 0.0;
    double vz = (tid < KNN) ? (double)sz[sh.order[tid]] : 0.0;
    double mx = tree_red(sh.red, tid, vx) / (double)KNN;
    double my = tree_red(sh.red, tid, vy) / (double)KNN;
    double mz = tree_red(sh.red, tid, vz) / (double)KNN;
    if (tid == 0) {
        d_gmean[gb][0] = mx; d_gmean[gb][1] = my; d_gmean[gb][2] = mz;
        float fmx = (float)mx, fmy = (float)my, fmz = (float)mz;
        d_meanf[gb][0] = fmx; d_meanf[gb][1] = fmy; d_meanf[gb][2] = fmz;
        double dxq = (double)fmx - (double)qx;
        double dyq = (double)fmy - (double)qy;
        double dzq = (double)fmz - (double)qz;
        sh.Dc = sqrt(dxq*dxq + dyq*dyq + dzq*dzq);
        sh.q2s[0] = fmx; sh.q2s[1] = fmy; sh.q2s[2] = fmz;
    }
    __syncthreads();

    // ---- pass 2 over survivors ----
    const float mxf = sh.q2s[0], myf = sh.q2s[1], mzf = sh.q2s[2];
    __syncthreads();
    for (int s = tid; s < S; s += NT) {
        float dx = sx[s]-mxf, dy = sy[s]-myf, dz = sz[s]-mzf;
        sd[s] = fmaf(dx, dx, fmaf(dy, dy, dz*dz));
    }
    __syncthreads();
    if (!select_topk(sd, si, hist, &sh, S, tid)) {
        if (tid == 0) d_flag[gb] = 2;
        return;
    }
    if (tid == 0) {
        float d100 = sd[sh.order[KNN-1]];
        double lhs = sh.Dc + sqrt((double)d100);
        if (lhs*lhs*(1.0 + 1e-4) < (double)Ta) {
            sh.bflag = 0;
            d_flag[gb] = 0;
        } else {
            sh.bflag = 1;
            d_flag[gb] = 1;
            d_T2[gb] = d100;
        }
    }
    __syncthreads();
    if (sh.bflag) return;

    cov_store(sx, sy, sz, &sh, tid, gb);
}

// ===========================================================================
// K3: fin. Per group: rescue (flag 1) / brute (flag 2) / nothing (0),
// then eigensolve; last block (ticket) computes the output scalar.
// ===========================================================================
__global__ void __launch_bounds__(NT) fin_kernel(const float* __restrict__ pts_all,
                                                 float* __restrict__ out) {
    extern __shared__ float dyn[];
    float* cX = dyn;
    float* cY = cX + FCAP;
    float* cZ = cY + FCAP;
    float* cD = cZ + FCAP;
    int*   cI = (int*)(cD + FCAP);
    unsigned* hist = (unsigned*)(cI + FCAP);
    __shared__ SelSh sh;
    __shared__ unsigned ncand;
    __shared__ float dirsS[NGB][3];
    __shared__ float gmfS[NGB][3];

    const int tid = threadIdx.x;
    const int gb  = blockIdx.x;
    const int flag = d_flag[gb];
    const int b = gb / NGRP, g = gb % NGRP;
    const float* __restrict__ pts = pts_all + (size_t)b * NPTS * 3;
    const float4* __restrict__ p4 = (const float4*)pts;

    if (flag == 1) {
        // exact rescue: ball {d2(mean) <= T2} over the whole cloud, in-block
        const float mxf = d_meanf[gb][0], myf = d_meanf[gb][1], mzf = d_meanf[gb][2];
        const float T2 = d_T2[gb];
        if (tid == 0) ncand = 0u;
        __syncthreads();
        #pragma unroll 2
        for (int it = tid; it < NPTS/4; it += NT) {
            float4 A = p4[3*it+0], B = p4[3*it+1], C = p4[3*it+2];
            float xs[4] = {A.x, A.w, B.z, C.y};
            float ys[4] = {A.y, B.x, B.w, C.z};
            float zs[4] = {A.z, B.y, C.x, C.w};
            #pragma unroll
            for (int k = 0; k < 4; k++) {
                float dx = xs[k]-mxf, dy = ys[k]-myf, dz = zs[k]-mzf;
                float d2 = fmaf(dx, dx, fmaf(dy, dy, dz*dz));
                if (d2 <= T2) {
                    unsigned s = atomicAdd(&ncand, 1u);
                    if (s < FCAP) {
                        cX[s] = xs[k]; cY[s] = ys[k]; cZ[s] = zs[k];
                        cD[s] = d2; cI[s] = 4*it + k;
                    }
                }
            }
        }
        __syncthreads();
        int C = (int)min(ncand, (unsigned)FCAP);
        select_topk(cD, cI, hist, &sh, C, tid);
        cov_store(cX, cY, cZ, &sh, tid, gb);
    } else if (flag == 2) {
        // brute exact fallback
        const int c0 = g * STRIDE;
        const float qx = pts[3*c0+0], qy = pts[3*c0+1], qz = pts[3*c0+2];
        for (int i = tid; i < HB; i += NT) hist[i] = 0u;
        __syncthreads();
        for (int it = tid; it < NPTS/4; it += NT) {
            float4 A = p4[3*it+0], B = p4[3*it+1], C = p4[3*it+2];
            float xs[4] = {A.x, A.w, B.z, C.y};
            float ys[4] = {A.y, B.x, B.w, C.z};
            float zs[4] = {A.z, B.y, C.x, C.w};
            #pragma unroll
            for (int k = 0; k < 4; k++) {
                float dx = xs[k]-qx, dy = ys[k]-qy, dz = zs[k]-qz;
                atomicAdd(&hist[d2bin(fmaf(dx, dx, fmaf(dy, dy, dz*dz)))], 1u);
            }
        }
        __syncthreads();
        {
            unsigned ps = 0;
            #pragma unroll
            for (int j = 0; j < HB/NT; j++) ps += hist[tid*(HB/NT) + j];
            sh.partial[tid] = ps;
        }
        __syncthreads();
        if (tid == 0) {
            unsigned c = 0; int t = 0;
            while (c + sh.partial[t] < KNN) { c += sh.partial[t]; t++; }
            int bin = t * (HB/NT);
            while (c + hist[bin] < KNN) { c += hist[bin]; bin++; }
            sh.pivotS = bin;
        }
        __syncthreads();
        const float edge1 = __uint_as_float(((unsigned)sh.pivotS + 1u) << 21);
        if (tid == 0) ncand = 0u;
        __syncthreads();
        for (int it = tid; it < NPTS/4; it += NT) {
            float4 A = p4[3*it+0], B = p4[3*it+1], C = p4[3*it+2];
            float xs[4] = {A.x, A.w, B.z, C.y};
            float ys[4] = {A.y, B.x, B.w, C.z};
            float zs[4] = {A.z, B.y, C.x, C.w};
            #pragma unroll
            for (int k = 0; k < 4; k++) {
                float dx = xs[k]-qx, dy = ys[k]-qy, dz = zs[k]-qz;
                float d2 = fmaf(dx, dx, fmaf(dy, dy, dz*dz));
                if (d2 < edge1) {
                    unsigned s = atomicAdd(&ncand, 1u);
                    if (s < FCAP) {
                        cX[s] = xs[k]; cY[s] = ys[k]; cZ[s] = zs[k];
                        cD[s] = d2; cI[s] = 4*it + k;
                    }
                }
            }
        }
        __syncthreads();
        int C1 = (int)min(ncand, (unsigned)FCAP);
        select_topk(cD, cI, hist, &sh, C1, tid);
        double vx = (tid < KNN) ? (double)cX[sh.order[tid]] : 0.0;
        double vy = (tid < KNN) ? (double)cY[sh.order[tid]] : 0.0;
        double vz = (tid < KNN) ? (double)cZ[sh.order[tid]] : 0.0;
        double mx = tree_red(sh.red, tid, vx) / (double)KNN;
        double my = tree_red(sh.red, tid, vy) / (double)KNN;
        double mz = tree_red(sh.red, tid, vz) / (double)KNN;
        if (tid == 0) {
            d_gmean[gb][0] = mx; d_gmean[gb][1] = my; d_gmean[gb][2] = mz;
            double dxq = mx - (double)qx, dyq = my - (double)qy, dzq = mz - (double)qz;
            double D  = sqrt(dxq*dxq + dyq*dyq + dzq*dzq);
            double r1 = sqrt((double)edge1);
            double R  = 2.0*D + r1;
            sh.q2s[0] = (float)mx; sh.q2s[1] = (float)my; sh.q2s[2] = (float)mz;
            sh.q2s[3] = (float)(R*R) * 1.0002f;
        }
        __syncthreads();
        const float q2x = sh.q2s[0], q2y = sh.q2s[1], q2z = sh.q2s[2];
        const float T2c = sh.q2s[3];
        __syncthreads();
        if (tid == 0) ncand = 0u;
        __syncthreads();
        for (int it = tid; it < NPTS/4; it += NT) {
            float4 A = p4[3*it+0], B = p4[3*it+1], C = p4[3*it+2];
            float xs[4] = {A.x, A.w, B.z, C.y};
            float ys[4] = {A.y, B.x, B.w, C.z};
            float zs[4] = {A.z, B.y, C.x, C.w};
            #pragma unroll
            for (int k = 0; k < 4; k++) {
                float dx = xs[k]-qx, dy = ys[k]-qy, dz = zs[k]-qz;
                float d2c = fmaf(dx, dx, fmaf(dy, dy, dz*dz));
                if (d2c < T2c) {
                    float ex = xs[k]-q2x, ey = ys[k]-q2y, ez = zs[k]-q2z;
                    float d2m = fmaf(ex, ex, fmaf(ey, ey, ez*ez));
                    unsigned s = atomicAdd(&ncand, 1u);
                    if (s < FCAP) {
                        cX[s] = xs[k]; cY[s] = ys[k]; cZ[s] = zs[k];
                        cD[s] = d2m; cI[s] = 4*it + k;
                    }
                }
            }
        }
        __syncthreads();
        int C2 = (int)min(ncand, (unsigned)FCAP);
        select_topk(cD, cI, hist, &sh, C2, tid);
        cov_store(cX, cY, cZ, &sh, tid, gb);
    }
    __syncthreads();

    // ---- eigensolve (all groups; cov in d_gcov) ----
    if (tid == 0) {
        double a00 = d_gcov[gb][0], a01 = d_gcov[gb][1], a02 = d_gcov[gb][2];
        double a11 = d_gcov[gb][3], a12 = d_gcov[gb][4], a22 = d_gcov[gb][5];
        double q  = (a00 + a11 + a22) / 3.0;
        double p1 = a01*a01 + a02*a02 + a12*a12;
        double b00 = a00 - q, b11 = a11 - q, b22 = a22 - q;
        double p2 = b00*b00 + b11*b11 + b22*b22 + 2.0*p1;
        double l1, l2, l3;
        if (p2 < 1e-60) {
            l1 = l2 = l3 = q;
        } else {
            double p  = sqrt(p2 / 6.0);
            double ip = 1.0 / p;
            double c00 = b00*ip, c11 = b11*ip, c22 = b22*ip;
            double c01 = a01*ip, c02 = a02*ip, c12 = a12*ip;
            double detB = c00*(c11*c22 - c12*c12)
                        - c01*(c01*c22 - c12*c02)
                        + c02*(c01*c12 - c11*c02);
            double r = 0.5 * detB;
            r = fmin(1.0, fmax(-1.0, r));
            double phi = (double)acosf((float)r) * (1.0/3.0);
            l3 = q + 2.0*p*(double)cosf((float)phi);
            l1 = q + 2.0*p*(double)cosf((float)(phi + 2.0943951023931953));
            l2 = 3.0*q - l1 - l3;
        }
        double denom = l1 + l2 + l3 + 1e-9;
        d_fs[gb] = (l3 - l2) / denom;

        double r0x = a00 - l3, r0y = a01,      r0z = a02;
        double r1x = a01,      r1y = a11 - l3, r1z = a12;
        double r2x = a02,      r2y = a12,      r2z = a22 - l3;
        double vax = r0y*r1z - r0z*r1y, vay = r0z*r1x - r0x*r1z, vaz = r0x*r1y - r0y*r1x;
        double vbx = r1y*r2z - r1z*r2y, vby = r1z*r2x - r1x*r2z, vbz = r1x*r2y - r1y*r2x;
        double vcx = r2y*r0z - r2z*r0y, vcy = r2z*r0x - r2x*r0z, vcz = r2x*r0y - r2y*r0x;
        double na = vax*vax + vay*vay + vaz*vaz;
        double nb = vbx*vbx + vby*vby + vbz*vbz;
        double nc = vcx*vcx + vcy*vcy + vcz*vcz;
        double vx, vy, vz, nn;
        if (na >= nb && na >= nc) { vx = vax; vy = vay; vz = vaz; nn = na; }
        else if (nb >= nc)        { vx = vbx; vy = vby; vz = vbz; nn = nb; }
        else                      { vx = vcx; vy = vcy; vz = vcz; nn = nc; }
        if (nn < 1e-300) { vx = 0.0; vy = 0.0; vz = 1.0; nn = 1.0; }
        double inn = rsqrt(nn);
        d_dirs[gb][0] = (float)(vx * inn);
        d_dirs[gb][1] = (float)(vy * inn);
        d_dirs[gb][2] = (float)(vz * inn);
    }
    __syncthreads();

    // ---- ticket: last block computes the output ----
    if (tid == 0) {
        __threadfence();
        unsigned t = atomicAdd(&d_ticket, 1u);
        sh.bflag = (t == NGB - 1) ? 1 : 0;
    }
    __syncthreads();
    if (!sh.bflag) return;
    __threadfence();

    double fs = 0.0;
    if (tid < NGB) {
        fs = d_fs[tid];
        dirsS[tid][0] = d_dirs[tid][0];
        dirsS[tid][1] = d_dirs[tid][1];
        dirsS[tid][2] = d_dirs[tid][2];
        gmfS[tid][0] = (float)d_gmean[tid][0];
        gmfS[tid][1] = (float)d_gmean[tid][1];
        gmfS[tid][2] = (float)d_gmean[tid][2];
    }
    __syncthreads();

    double term = 0.0;
    if (tid < NGB) {
        int bb = tid / NGRP, gg = tid % NGRP;
        float qx = gmfS[tid][0], qy = gmfS[tid][1], qz = gmfS[tid][2];
        float best = 3.4e38f; int bj = 0;
        for (int o = 0; o < NGRP; o++) {
            float dx = qx - gmfS[bb*NGRP+o][0];
            float dy = qy - gmfS[bb*NGRP+o][1];
            float dz = qz - gmfS[bb*NGRP+o][2];
            float dd = dx*dx + dy*dy + dz*dz;
            if (o == gg) dd += 1e30f;
            if (dd < best) { best = dd; bj = o; }
        }
        int j = bb*NGRP + bj;
        float cs = dirsS[tid][0]*dirsS[j][0] + dirsS[tid][1]*dirsS[j][1] + dirsS[tid][2]*dirsS[j][2];
        term = 1.0 - (double)cs * (double)cs;
    }

    double sumfs = tree_red(sh.red, tid, fs);
    double sumterm = tree_red(sh.red, tid, term);
    if (tid == 0) out[0] = (float)(-sumfs / (double)NBATCH + sumterm / (double)NGB);
}

extern "C" void kernel_launch(void* const* d_in, const int* in_sizes, int n_in,
                              void* d_out, int out_size) {
    const float* pts = (const float*)d_in[0];
    float* out = (float*)d_out;
    cudaFuncSetAttribute(select_kernel, cudaFuncAttributeMaxDynamicSharedMemorySize, SEL_DYN);
    cudaFuncSetAttribute(fin_kernel, cudaFuncAttributeMaxDynamicSharedMemorySize, FIN_DYN);
    scan_kernel<<<NBATCH*GT*PTC, NT>>>(pts);
    select_kernel<<<NGB, NT, SEL_DYN>>>(pts);
    fin_kernel<<<NGB, NT, FIN_DYN>>>(pts, out);
}

// round 9
// speedup vs baseline: 2.6844x; 1.1188x over previous
#include <cuda_runtime.h>
#include <math.h>

#define NBATCH 8
#define NPTS   131072
#define NGRP   30
#define NGB    (NBATCH*NGRP)   // 240
#define KNN    100
#define STRIDE 4369            // 131072/30
#define HB     2048            // float-radix bins: bits(d2) >> 21
#define GPT    6               // groups per tile
#define GT     5               // tiles
#define PTC    16              // point chunks
#define CHUNK  (NPTS/PTC)      // 8192
#define NT     256
#define MTGT   700.0f

#define SEGCAP 128             // per-(group,chunk) survivor segment
#define SELCAP (PTC*SEGCAP)    // 2048 max total survivors
#define SUBCAP 1024
#define FCAP   4096            // rescue/brute candidate buffer

#define SF_DYN ((5*FCAP + HB)*4)   // 88 KB (>= select view (5*SELCAP+HB)*4)

// -------- static device scratch --------
__device__ float    d_Ta[NGB];
__device__ unsigned d_segcnt[NGB][PTC];
__device__ float4   d_seg[NGB][PTC][SEGCAP];
__device__ double   d_gmean[NGB][3];
__device__ double   d_gcov[NGB][6];
__device__ float    d_dirs[NGB][3];
__device__ double   d_fs[NGB];
__device__ unsigned d_ticket;

__device__ __forceinline__ unsigned d2bin(float d2) {
    return __float_as_uint(d2) >> 21;
}

// ===========================================================================
// K1: scan. Each block = (batch, 6-group tile, chunk). Radii via bisection on
// the closed-form noncentral distance CDF; survivors -> private segments.
// ===========================================================================
__global__ void __launch_bounds__(NT) scan_kernel(const float* __restrict__ pts_all) {
    __shared__ float ta[GPT], qxs[GPT], qys[GPT], qzs[GPT];
    __shared__ unsigned scnt[GPT];
    const int bidx = blockIdx.x;
    const int pc = bidx % PTC;
    const int gt = (bidx / PTC) % GT;
    const int b  = bidx / (PTC * GT);
    const float* __restrict__ pts = pts_all + (size_t)b * NPTS * 3;
    const float4* __restrict__ p4 = (const float4*)pts;
    const int gbase = b * NGRP + gt * GPT;
    const int tid = threadIdx.x;

    if (tid < GPT) {
        int ci = (gt*GPT + tid) * STRIDE;
        float qx = pts[3*ci], qy = pts[3*ci+1], qz = pts[3*ci+2];
        qxs[tid] = qx; qys[tid] = qy; qzs[tid] = qz;
        float rho = fmaxf(sqrtf(qx*qx + qy*qy + qz*qz), 0.02f);
        const float tgt = MTGT / (float)NPTS;
        const float irho = 0.3989423f / rho;
        float lo = 0.01f, hi = 6.0f;
        #pragma unroll 1
        for (int it = 0; it < 30; it++) {
            float s = 0.5f*(lo + hi);
            float a = s - rho, c = s + rho;
            float F = 0.5f*erff(a*0.70710678f) + 0.5f*erff(c*0.70710678f)
                    - (expf(-0.5f*a*a) - expf(-0.5f*c*c)) * irho;
            if (F >= tgt) hi = s; else lo = s;
        }
        ta[tid] = hi * hi;
        d_Ta[gbase + tid] = hi * hi;      // duplicate identical writes OK
        scnt[tid] = 0u;
    }
    if (bidx == 0 && tid == 0) d_ticket = 0u;
    __syncthreads();

    float qx[GPT], qy[GPT], qz[GPT], tta[GPT];
    #pragma unroll
    for (int j = 0; j < GPT; j++) { qx[j]=qxs[j]; qy[j]=qys[j]; qz[j]=qzs[j]; tta[j]=ta[j]; }

    const int q0 = pc * (CHUNK/4);
    for (int it = q0 + tid; it < q0 + CHUNK/4; it += NT) {
        float4 A = p4[3*it+0];
        float4 B = p4[3*it+1];
        float4 C = p4[3*it+2];
        float xs[4] = {A.x, A.w, B.z, C.y};
        float ys[4] = {A.y, B.x, B.w, C.z};
        float zs[4] = {A.z, B.y, C.x, C.w};
        #pragma unroll
        for (int k = 0; k < 4; k++) {
            #pragma unroll
            for (int j = 0; j < GPT; j++) {
                float dx = xs[k]-qx[j], dy = ys[k]-qy[j], dz = zs[k]-qz[j];
                float d2 = fmaf(dx, dx, fmaf(dy, dy, dz*dz));
                if (d2 < tta[j]) {
                    unsigned s = atomicAdd(&scnt[j], 1u);
                    if (s < SEGCAP)
                        d_seg[gbase + j][pc][s] = make_float4(xs[k], ys[k], zs[k],
                                                              __int_as_float(4*it + k));
                }
            }
        }
    }
    __syncthreads();
    if (tid < GPT) d_segcnt[gbase + tid][pc] = scnt[tid];
}

// ===========================================================================
// shared selection machinery
// ===========================================================================
struct SelSh {
    unsigned partial[NT];
    int      subSlot[SUBCAP];
    int      order[KNN];
    double   red[NT];
    float    q2s[4];
    double   Dc;
    unsigned nsub;
    int      pivotS;
    int      bflag;
};

__device__ __forceinline__ double tree_red(double* red, int tid, double v) {
    red[tid] = v;
    __syncthreads();
    #pragma unroll
    for (int s = NT/2; s > 0; s >>= 1) {
        if (tid < s) red[tid] += red[tid + s];
        __syncthreads();
    }
    double r = red[0];
    __syncthreads();
    return r;
}

__device__ __forceinline__ bool select_topk(const float* sd, const int* si,
                                            unsigned* hist, SelSh* sh,
                                            int S, int tid) {
    for (int i = tid; i < HB; i += NT) hist[i] = 0u;
    if (tid == 0) sh->nsub = 0u;
    __syncthreads();
    for (int s = tid; s < S; s += NT) atomicAdd(&hist[d2bin(sd[s])], 1u);
    __syncthreads();
    {
        unsigned ps = 0;
        #pragma unroll
        for (int j = 0; j < HB/NT; j++) ps += hist[tid*(HB/NT) + j];
        sh->partial[tid] = ps;
    }
    __syncthreads();
    if (tid == 0) {
        unsigned c = 0; int t = 0;
        while (c + sh->partial[t] < KNN) { c += sh->partial[t]; t++; }
        int bin = t * (HB/NT);
        while (c + hist[bin] < KNN) { c += hist[bin]; bin++; }
        sh->pivotS = bin;
    }
    __syncthreads();
    const unsigned piv = (unsigned)sh->pivotS;
    for (int s = tid; s < S; s += NT) {
        if (d2bin(sd[s]) <= piv) {
            unsigned u = atomicAdd(&sh->nsub, 1u);
            if (u < SUBCAP) sh->subSlot[u] = s;
        }
    }
    __syncthreads();
    bool ok = (sh->nsub <= SUBCAP);
    const int U = (int)min(sh->nsub, (unsigned)SUBCAP);
    for (int u = tid; u < U; u += NT) {
        int slot = sh->subSlot[u];
        float d = sd[slot]; int id = si[slot];
        int rank = 0;
        for (int v = 0; v < U; v++) {
            int s2 = sh->subSlot[v];
            float dv = sd[s2];
            rank += (dv < d) || (dv == d && si[s2] < id);
        }
        if (rank < KNN) sh->order[rank] = slot;
    }
    __syncthreads();
    return ok;
}

__device__ __forceinline__ void cov_store(const float* sx, const float* sy,
                                          const float* sz, SelSh* sh,
                                          int tid, int gb) {
    double X = (tid < KNN) ? (double)sx[sh->order[tid]] : 0.0;
    double Y = (tid < KNN) ? (double)sy[sh->order[tid]] : 0.0;
    double Z = (tid < KNN) ? (double)sz[sh->order[tid]] : 0.0;
    double s0 = tree_red(sh->red, tid, X);
    double s1 = tree_red(sh->red, tid, Y);
    double s2 = tree_red(sh->red, tid, Z);
    double s3 = tree_red(sh->red, tid, X*X);
    double s4 = tree_red(sh->red, tid, X*Y);
    double s5 = tree_red(sh->red, tid, X*Z);
    double s6 = tree_red(sh->red, tid, Y*Y);
    double s7 = tree_red(sh->red, tid, Y*Z);
    double s8 = tree_red(sh->red, tid, Z*Z);
    if (tid == 0) {
        const double K = (double)KNN;
        double ax = s0/K, ay = s1/K, az = s2/K;
        d_gcov[gb][0] = s3/K - ax*ax;
        d_gcov[gb][1] = s4/K - ax*ay;
        d_gcov[gb][2] = s5/K - ax*az;
        d_gcov[gb][3] = s6/K - ay*ay;
        d_gcov[gb][4] = s7/K - ay*az;
        d_gcov[gb][5] = s8/K - az*az;
    }
}

// ===========================================================================
// K2: selfin. Select (exact 2-pass over survivors) -> inline rescue/brute if
// flagged -> eigensolve -> ticket; last block reduces the output scalar.
// ===========================================================================
__global__ void __launch_bounds__(NT) selfin_kernel(const float* __restrict__ pts_all,
                                                    float* __restrict__ out) {
    extern __shared__ float dyn[];
    // select view
    float* sx = dyn;
    float* sy = sx + SELCAP;
    float* sz = sy + SELCAP;
    float* sd = sz + SELCAP;
    int*   si = (int*)(sd + SELCAP);
    unsigned* histS = (unsigned*)(si + SELCAP);
    // rescue/brute view (reuses same dyn range; only used after select done)
    float* cX = dyn;
    float* cY = cX + FCAP;
    float* cZ = cY + FCAP;
    float* cD = cZ + FCAP;
    int*   cI = (int*)(cD + FCAP);
    unsigned* histF = (unsigned*)(cI + FCAP);

    __shared__ SelSh sh;
    __shared__ unsigned offs[PTC+1];
    __shared__ unsigned ncand;
    __shared__ int gflag;
    __shared__ float sT2;
    __shared__ float dirsS[NGB][3];
    __shared__ float gmfS[NGB][3];

    const int tid = threadIdx.x;
    const int gb  = blockIdx.x;
    const int b = gb / NGRP, g = gb % NGRP;
    const float* __restrict__ pts = pts_all + (size_t)b * NPTS * 3;
    const float4* __restrict__ p4 = (const float4*)pts;
    const int ci = g * STRIDE;
    const float qx = pts[3*ci], qy = pts[3*ci+1], qz = pts[3*ci+2];
    const float Ta = d_Ta[gb];

    // ---------------- select phase ----------------
    if (tid == 0) {
        unsigned o = 0; int bad = 0;
        for (int pc = 0; pc < PTC; pc++) {
            unsigned c = d_segcnt[gb][pc];
            if (c > SEGCAP) bad = 1;
            offs[pc] = o; o += (c > SEGCAP ? SEGCAP : c);
        }
        offs[PTC] = o;
        gflag = (bad || o < KNN) ? 2 : 0;
    }
    __syncthreads();

    if (gflag == 0) {
        const int S = (int)offs[PTC];
        for (int pc = 0; pc < PTC; pc++) {
            unsigned base = offs[pc], cnt = offs[pc+1] - offs[pc];
            for (unsigned u = tid; u < cnt; u += NT) {
                float4 v = d_seg[gb][pc][u];
                sx[base+u] = v.x; sy[base+u] = v.y; sz[base+u] = v.z;
                si[base+u] = __float_as_int(v.w);
            }
        }
        __syncthreads();
        for (int s = tid; s < S; s += NT) {
            float dx = sx[s]-qx, dy = sy[s]-qy, dz = sz[s]-qz;
            sd[s] = fmaf(dx, dx, fmaf(dy, dy, dz*dz));
        }
        __syncthreads();

        // pass 1 (survivors = ALL points < Ta, exact)
        if (!select_topk(sd, si, histS, &sh, S, tid)) {
            if (tid == 0) gflag = 2;
            __syncthreads();
        }
        if (gflag == 0) {
            double vx = (tid < KNN) ? (double)sx[sh.order[tid]] : 0.0;
            double vy = (tid < KNN) ? (double)sy[sh.order[tid]] : 0.0;
            double vz = (tid < KNN) ? (double)sz[sh.order[tid]] : 0.0;
            double mx = tree_red(sh.red, tid, vx) / (double)KNN;
            double my = tree_red(sh.red, tid, vy) / (double)KNN;
            double mz = tree_red(sh.red, tid, vz) / (double)KNN;
            if (tid == 0) {
                d_gmean[gb][0] = mx; d_gmean[gb][1] = my; d_gmean[gb][2] = mz;
                float fmx = (float)mx, fmy = (float)my, fmz = (float)mz;
                double dxq = (double)fmx - (double)qx;
                double dyq = (double)fmy - (double)qy;
                double dzq = (double)fmz - (double)qz;
                sh.Dc = sqrt(dxq*dxq + dyq*dyq + dzq*dzq);
                sh.q2s[0] = fmx; sh.q2s[1] = fmy; sh.q2s[2] = fmz;
            }
            __syncthreads();

            // pass 2 over survivors
            const float mxf = sh.q2s[0], myf = sh.q2s[1], mzf = sh.q2s[2];
            __syncthreads();
            for (int s = tid; s < S; s += NT) {
                float dx = sx[s]-mxf, dy = sy[s]-myf, dz = sz[s]-mzf;
                sd[s] = fmaf(dx, dx, fmaf(dy, dy, dz*dz));
            }
            __syncthreads();
            if (!select_topk(sd, si, histS, &sh, S, tid)) {
                if (tid == 0) gflag = 2;
                __syncthreads();
            }
            if (gflag == 0) {
                if (tid == 0) {
                    float d100 = sd[sh.order[KNN-1]];
                    double lhs = sh.Dc + sqrt((double)d100);
                    if (lhs*lhs*(1.0 + 1e-4) < (double)Ta) {
                        gflag = 0;
                    } else {
                        gflag = 1;
                        sT2 = d100;
                    }
                }
                __syncthreads();
                if (gflag == 0) cov_store(sx, sy, sz, &sh, tid, gb);
            }
        }
    }
    __syncthreads();

    // ---------------- rescue (flag 1): exact ball over whole cloud ----------
    if (gflag == 1) {
        const float mxf = sh.q2s[0], myf = sh.q2s[1], mzf = sh.q2s[2];
        const float T2 = sT2;
        __syncthreads();   // protect dyn reuse
        if (tid == 0) ncand = 0u;
        __syncthreads();
        #pragma unroll 2
        for (int it = tid; it < NPTS/4; it += NT) {
            float4 A = p4[3*it+0], B = p4[3*it+1], C = p4[3*it+2];
            float xs[4] = {A.x, A.w, B.z, C.y};
            float ys[4] = {A.y, B.x, B.w, C.z};
            float zs[4] = {A.z, B.y, C.x, C.w};
            #pragma unroll
            for (int k = 0; k < 4; k++) {
                float dx = xs[k]-mxf, dy = ys[k]-myf, dz = zs[k]-mzf;
                float d2 = fmaf(dx, dx, fmaf(dy, dy, dz*dz));
                if (d2 <= T2) {
                    unsigned s = atomicAdd(&ncand, 1u);
                    if (s < FCAP) {
                        cX[s] = xs[k]; cY[s] = ys[k]; cZ[s] = zs[k];
                        cD[s] = d2; cI[s] = 4*it + k;
                    }
                }
            }
        }
        __syncthreads();
        if (ncand > FCAP) { if (tid == 0) gflag = 2; __syncthreads(); }
        else {
            int C = (int)ncand;
            select_topk(cD, cI, histF, &sh, C, tid);
            cov_store(cX, cY, cZ, &sh, tid, gb);
        }
    }

    // ---------------- brute (flag 2): exact full fallback -------------------
    if (gflag == 2) {
        __syncthreads();
        for (int i = tid; i < HB; i += NT) histF[i] = 0u;
        __syncthreads();
        for (int it = tid; it < NPTS/4; it += NT) {
            float4 A = p4[3*it+0], B = p4[3*it+1], C = p4[3*it+2];
            float xs[4] = {A.x, A.w, B.z, C.y};
            float ys[4] = {A.y, B.x, B.w, C.z};
            float zs[4] = {A.z, B.y, C.x, C.w};
            #pragma unroll
            for (int k = 0; k < 4; k++) {
                float dx = xs[k]-qx, dy = ys[k]-qy, dz = zs[k]-qz;
                atomicAdd(&histF[d2bin(fmaf(dx, dx, fmaf(dy, dy, dz*dz)))], 1u);
            }
        }
        __syncthreads();
        {
            unsigned ps = 0;
            #pragma unroll
            for (int j = 0; j < HB/NT; j++) ps += histF[tid*(HB/NT) + j];
            sh.partial[tid] = ps;
        }
        __syncthreads();
        if (tid == 0) {
            unsigned c = 0; int t = 0;
            while (c + sh.partial[t] < KNN) { c += sh.partial[t]; t++; }
            int bin = t * (HB/NT);
            while (c + histF[bin] < KNN) { c += histF[bin]; bin++; }
            sh.pivotS = bin;
        }
        __syncthreads();
        const float edge1 = __uint_as_float(((unsigned)sh.pivotS + 1u) << 21);
        if (tid == 0) ncand = 0u;
        __syncthreads();
        for (int it = tid; it < NPTS/4; it += NT) {
            float4 A = p4[3*it+0], B = p4[3*it+1], C = p4[3*it+2];
            float xs[4] = {A.x, A.w, B.z, C.y};
            float ys[4] = {A.y, B.x, B.w, C.z};
            float zs[4] = {A.z, B.y, C.x, C.w};
            #pragma unroll
            for (int k = 0; k < 4; k++) {
                float dx = xs[k]-qx, dy = ys[k]-qy, dz = zs[k]-qz;
                float d2 = fmaf(dx, dx, fmaf(dy, dy, dz*dz));
                if (d2 < edge1) {
                    unsigned s = atomicAdd(&ncand, 1u);
                    if (s < FCAP) {
                        cX[s] = xs[k]; cY[s] = ys[k]; cZ[s] = zs[k];
                        cD[s] = d2; cI[s] = 4*it + k;
                    }
                }
            }
        }
        __syncthreads();
        int C1 = (int)min(ncand, (unsigned)FCAP);
        select_topk(cD, cI, histF, &sh, C1, tid);
        double vx = (tid < KNN) ? (double)cX[sh.order[tid]] : 0.0;
        double vy = (tid < KNN) ? (double)cY[sh.order[tid]] : 0.0;
        double vz = (tid < KNN) ? (double)cZ[sh.order[tid]] : 0.0;
        double mx = tree_red(sh.red, tid, vx) / (double)KNN;
        double my = tree_red(sh.red, tid, vy) / (double)KNN;
        double mz = tree_red(sh.red, tid, vz) / (double)KNN;
        if (tid == 0) {
            d_gmean[gb][0] = mx; d_gmean[gb][1] = my; d_gmean[gb][2] = mz;
            double dxq = mx - (double)qx, dyq = my - (double)qy, dzq = mz - (double)qz;
            double D  = sqrt(dxq*dxq + dyq*dyq + dzq*dzq);
            double r1 = sqrt((double)edge1);
            double R  = 2.0*D + r1;
            sh.q2s[0] = (float)mx; sh.q2s[1] = (float)my; sh.q2s[2] = (float)mz;
            sh.q2s[3] = (float)(R*R) * 1.0002f;
        }
        __syncthreads();
        const float q2x = sh.q2s[0], q2y = sh.q2s[1], q2z = sh.q2s[2];
        const float T2c = sh.q2s[3];
        __syncthreads();
        if (tid == 0) ncand = 0u;
        __syncthreads();
        for (int it = tid; it < NPTS/4; it += NT) {
            float4 A = p4[3*it+0], B = p4[3*it+1], C = p4[3*it+2];
            float xs[4] = {A.x, A.w, B.z, C.y};
            float ys[4] = {A.y, B.x, B.w, C.z};
            float zs[4] = {A.z, B.y, C.x, C.w};
            #pragma unroll
            for (int k = 0; k < 4; k++) {
                float dx = xs[k]-qx, dy = ys[k]-qy, dz = zs[k]-qz;
                float d2c = fmaf(dx, dx, fmaf(dy, dy, dz*dz));
                if (d2c < T2c) {
                    float ex = xs[k]-q2x, ey = ys[k]-q2y, ez = zs[k]-q2z;
                    float d2m = fmaf(ex, ex, fmaf(ey, ey, ez*ez));
                    unsigned s = atomicAdd(&ncand, 1u);
                    if (s < FCAP) {
                        cX[s] = xs[k]; cY[s] = ys[k]; cZ[s] = zs[k];
                        cD[s] = d2m; cI[s] = 4*it + k;
                    }
                }
            }
        }
        __syncthreads();
        int C2 = (int)min(ncand, (unsigned)FCAP);
        select_topk(cD, cI, histF, &sh, C2, tid);
        cov_store(cX, cY, cZ, &sh, tid, gb);
    }
    __syncthreads();

    // ---------------- eigensolve ----------------
    if (tid == 0) {
        double a00 = d_gcov[gb][0], a01 = d_gcov[gb][1], a02 = d_gcov[gb][2];
        double a11 = d_gcov[gb][3], a12 = d_gcov[gb][4], a22 = d_gcov[gb][5];
        double q  = (a00 + a11 + a22) / 3.0;
        double p1 = a01*a01 + a02*a02 + a12*a12;
        double b00 = a00 - q, b11 = a11 - q, b22 = a22 - q;
        double p2 = b00*b00 + b11*b11 + b22*b22 + 2.0*p1;
        double l1, l2, l3;
        if (p2 < 1e-60) {
            l1 = l2 = l3 = q;
        } else {
            double p  = sqrt(p2 / 6.0);
            double ip = 1.0 / p;
            double c00 = b00*ip, c11 = b11*ip, c22 = b22*ip;
            double c01 = a01*ip, c02 = a02*ip, c12 = a12*ip;
            double detB = c00*(c11*c22 - c12*c12)
                        - c01*(c01*c22 - c12*c02)
                        + c02*(c01*c12 - c11*c02);
            double r = 0.5 * detB;
            r = fmin(1.0, fmax(-1.0, r));
            double phi = (double)acosf((float)r) * (1.0/3.0);
            l3 = q + 2.0*p*(double)cosf((float)phi);
            l1 = q + 2.0*p*(double)cosf((float)(phi + 2.0943951023931953));
            l2 = 3.0*q - l1 - l3;
        }
        double denom = l1 + l2 + l3 + 1e-9;
        d_fs[gb] = (l3 - l2) / denom;

        double r0x = a00 - l3, r0y = a01,      r0z = a02;
        double r1x = a01,      r1y = a11 - l3, r1z = a12;
        double r2x = a02,      r2y = a12,      r2z = a22 - l3;
        double vax = r0y*r1z - r0z*r1y, vay = r0z*r1x - r0x*r1z, vaz = r0x*r1y - r0y*r1x;
        double vbx = r1y*r2z - r1z*r2y, vby = r1z*r2x - r1x*r2z, vbz = r1x*r2y - r1y*r2x;
        double vcx = r2y*r0z - r2z*r0y, vcy = r2z*r0x - r2x*r0z, vcz = r2x*r0y - r2y*r0x;
        double na = vax*vax + vay*vay + vaz*vaz;
        double nb = vbx*vbx + vby*vby + vbz*vbz;
        double nc = vcx*vcx + vcy*vcy + vcz*vcz;
        double vx2, vy2, vz2, nn;
        if (na >= nb && na >= nc) { vx2 = vax; vy2 = vay; vz2 = vaz; nn = na; }
        else if (nb >= nc)        { vx2 = vbx; vy2 = vby; vz2 = vbz; nn = nb; }
        else                      { vx2 = vcx; vy2 = vcy; vz2 = vcz; nn = nc; }
        if (nn < 1e-300) { vx2 = 0.0; vy2 = 0.0; vz2 = 1.0; nn = 1.0; }
        double inn = rsqrt(nn);
        d_dirs[gb][0] = (float)(vx2 * inn);
        d_dirs[gb][1] = (float)(vy2 * inn);
        d_dirs[gb][2] = (float)(vz2 * inn);
    }
    __syncthreads();

    // ---------------- ticket: last block reduces the output ----------------
    if (tid == 0) {
        __threadfence();
        unsigned t = atomicAdd(&d_ticket, 1u);
        gflag = (t == NGB - 1) ? -1 : 0;
    }
    __syncthreads();
    if (gflag != -1) return;
    __threadfence();

    double fs = 0.0;
    if (tid < NGB) {
        fs = d_fs[tid];
        dirsS[tid][0] = d_dirs[tid][0];
        dirsS[tid][1] = d_dirs[tid][1];
        dirsS[tid][2] = d_dirs[tid][2];
        gmfS[tid][0] = (float)d_gmean[tid][0];
        gmfS[tid][1] = (float)d_gmean[tid][1];
        gmfS[tid][2] = (float)d_gmean[tid][2];
    }
    __syncthreads();

    double term = 0.0;
    if (tid < NGB) {
        int bb = tid / NGRP, gg = tid % NGRP;
        float qx2 = gmfS[tid][0], qy2 = gmfS[tid][1], qz2 = gmfS[tid][2];
        float best = 3.4e38f; int bj = 0;
        for (int o = 0; o < NGRP; o++) {
            float dx = qx2 - gmfS[bb*NGRP+o][0];
            float dy = qy2 - gmfS[bb*NGRP+o][1];
            float dz = qz2 - gmfS[bb*NGRP+o][2];
            float dd = dx*dx + dy*dy + dz*dz;
            if (o == gg) dd += 1e30f;
            if (dd < best) { best = dd; bj = o; }
        }
        int j = bb*NGRP + bj;
        float cs = dirsS[tid][0]*dirsS[j][0] + dirsS[tid][1]*dirsS[j][1] + dirsS[tid][2]*dirsS[j][2];
        term = 1.0 - (double)cs * (double)cs;
    }

    double sumfs = tree_red(sh.red, tid, fs);
    double sumterm = tree_red(sh.red, tid, term);
    if (tid == 0) out[0] = (float)(-sumfs / (double)NBATCH + sumterm / (double)NGB);
}

extern "C" void kernel_launch(void* const* d_in, const int* in_sizes, int n_in,
                              void* d_out, int out_size) {
    const float* pts = (const float*)d_in[0];
    float* out = (float*)d_out;
    cudaFuncSetAttribute(selfin_kernel, cudaFuncAttributeMaxDynamicSharedMemorySize, SF_DYN);
    scan_kernel<<<NBATCH*GT*PTC, NT>>>(pts);
    selfin_kernel<<<NGB, NT, SF_DYN>>>(pts, out);
}